// round 6
// baseline (speedup 1.0000x reference)
#include <cuda_runtime.h>
#include <cuda_bf16.h>
#include <cstdint>

#define BB   16
#define TT   128
#define VV   32000
#define HH   512
#define LL   2
#define DD   8
#define AH   256
#define G4   2048
#define PAD_ID 0
#define EOS_ID 3
#define NROW (BB*TT)            // 2048
#define BTV  ((size_t)NROW*VV)

// ---------------- device scratch ----------------
__device__ float g_scores[BB*DD*LL];
__device__ float g_ctx[BB*LL*HH];
__device__ float g_K[LL*BB*G4];
__device__ float g_Xe[NROW*HH];
__device__ float g_gx0[(size_t)NROW*G4];
__device__ float g_X[NROW*HH];
__device__ float g_h0[2][BB*HH];
__device__ float g_h1[2][BB*HH];
__device__ float g_c0[BB*HH];
__device__ float g_c1[BB*HH];
__device__ float g_rowmax[NROW];
__device__ int   g_argidx[NROW];
__device__ int   g_mask[NROW];
__device__ unsigned g_bcnt = 0;
__device__ unsigned g_bgen = 0;

__device__ __forceinline__ float sigf(float x){ return 1.0f/(1.0f+__expf(-x)); }

// grid barrier (all CTAs resident)
__device__ __forceinline__ void gbar() {
    __threadfence();
    __syncthreads();
    if (threadIdx.x == 0) {
        volatile unsigned* vg = &g_bgen;
        unsigned g = *vg;
        unsigned a = atomicAdd(&g_bcnt, 1u);
        if (a == gridDim.x - 1u) {
            g_bcnt = 0;
            __threadfence();
            atomicAdd(&g_bgen, 1u);
        } else {
            while (*vg == g) { __nanosleep(64); }
        }
        __threadfence();
    }
    __syncthreads();
}

// ---------------- K1: attention scores  blk=(b*D+d)*L+l ----------------
__global__ void k_attn_scores(const float* __restrict__ emb, const float* __restrict__ W1,
                              const float* __restrict__ b1, const float* __restrict__ W2,
                              const float* __restrict__ b2) {
    __shared__ float se[HH];
    __shared__ float red[AH];
    int blk = blockIdx.x;
    const float* ep = emb + (size_t)blk * HH;
    for (int i = threadIdx.x; i < HH; i += AH) se[i] = ep[i];
    __syncthreads();
    int a = threadIdx.x;
    const float* w1 = W1 + (size_t)a * HH;
    float dot = 0.f;
    #pragma unroll 8
    for (int k = 0; k < HH; k++) dot += se[k] * w1[k];
    red[a] = tanhf(dot + b1[a]) * W2[a];
    __syncthreads();
    for (int s = AH/2; s > 0; s >>= 1) {
        if (a < s) red[a] += red[a + s];
        __syncthreads();
    }
    if (a == 0) g_scores[blk] = red[0] + b2[0];
}

// ---------------- K2: softmax over docs + context ----------------
__global__ void k_attn_ctx(const float* __restrict__ emb) {
    int b = blockIdx.x >> 1, l = blockIdx.x & 1;
    __shared__ float s[DD];
    if (threadIdx.x < DD) s[threadIdx.x] = g_scores[(b*DD + threadIdx.x)*LL + l];
    __syncthreads();
    float mx = -1e30f;
    #pragma unroll
    for (int d = 0; d < DD; d++) mx = fmaxf(mx, s[d]);
    float w[DD]; float sum = 0.f;
    #pragma unroll
    for (int d = 0; d < DD; d++) { w[d] = __expf(s[d] - mx); sum += w[d]; }
    float inv = 1.0f / sum;
    for (int h = threadIdx.x; h < HH; h += 256) {
        float acc = 0.f;
        #pragma unroll
        for (int d = 0; d < DD; d++)
            acc += w[d] * inv * emb[((size_t)(b*DD + d)*LL + l)*HH + h];
        g_ctx[(b*LL + l)*HH + h] = acc;
    }
}

// ---------------- K3: K[l][b][g] = 0.5*ctx@Whh^T + b_ih + b_hh ----------------
__global__ void k_ctx_gates(const float* __restrict__ Whh, const float* __restrict__ bih,
                            const float* __restrict__ bhh) {
    int out  = blockIdx.x * 8 + (threadIdx.x >> 5);
    int lane = threadIdx.x & 31;
    int l = out >> 15;
    int b = (out >> 11) & 15;
    int g = out & 2047;
    const float* wr = Whh + (size_t)l*G4*HH + (size_t)g*HH;
    const float* cx = g_ctx + (b*LL + l)*HH;
    float acc = 0.f;
    for (int k = lane; k < HH; k += 32) acc += wr[k]*cx[k];
    #pragma unroll
    for (int o = 16; o > 0; o >>= 1) acc += __shfl_xor_sync(0xffffffffu, acc, o);
    if (lane == 0) g_K[out] = 0.5f*acc + bih[l*G4 + g] + bhh[l*G4 + g];
}

// ---------------- K4: embedding gather ----------------
__global__ void k_embed(const int* __restrict__ init_input, const int* __restrict__ targets,
                        const float* __restrict__ embW) {
    int i4 = blockIdx.x * 256 + threadIdx.x;       // over B*T*H/4
    if (i4 >= BB*TT*HH/4) return;
    int r  = i4 >> 7;
    int h4 = i4 & 127;
    int b = r >> 7, t = r & 127;
    int tok = (t == 0) ? init_input[b] : targets[b*TT + t - 1];
    ((float4*)g_Xe)[i4] = ((const float4*)(embW + (size_t)tok*HH))[h4];
}

// ---------------- tf32-split tensor-core GEMM (NT) ----------------
// C[M x N] = A[M x 512] * B[N x 512]^T (+bias), fp32 accuracy via hi/lo split.
// CTA tile 128x256, BK=32, 8 warps (2 in M x 4 in N), warp tile 64x64.
__device__ __forceinline__ uint32_t cvt_tf32(float v) {
    uint32_t r; asm("cvt.rna.tf32.f32 %0, %1;" : "=r"(r) : "f"(v)); return r;
}
__device__ __forceinline__ void mma8(float& c0, float& c1, float& c2, float& c3,
                                     uint32_t a0, uint32_t a1, uint32_t a2, uint32_t a3,
                                     uint32_t b0, uint32_t b1) {
    asm volatile("mma.sync.aligned.m16n8k8.row.col.f32.tf32.tf32.f32 "
        "{%0,%1,%2,%3}, {%4,%5,%6,%7}, {%8,%9}, {%0,%1,%2,%3};"
        : "+f"(c0), "+f"(c1), "+f"(c2), "+f"(c3)
        : "r"(a0), "r"(a1), "r"(a2), "r"(a3), "r"(b0), "r"(b1));
}
__device__ __forceinline__ void cpasync16(uint32_t s, const void* g) {
    asm volatile("cp.async.ca.shared.global [%0], [%1], 16;" :: "r"(s), "l"(g));
}

#define ASTR 36
#define ABUF (128*ASTR)
#define BBUF (256*ASTR)
#define STG  (ABUF + BBUF)

__global__ __launch_bounds__(256) void k_mma_nt(const float* __restrict__ A,
        const float* __restrict__ Bw, const float* __restrict__ bias,
        float* __restrict__ C, int N) {
    extern __shared__ float sm[];
    int tid = threadIdx.x, lane = tid & 31, wid = tid >> 5;
    int wm = wid & 1, wn = wid >> 1;
    size_t bm = (size_t)blockIdx.y * 128;
    size_t bn = (size_t)blockIdx.x * 256;

    int sc   = (tid & 7) * 4;     // k offset within BK
    int srow = tid >> 3;          // 0..31
    const float* Ag = A  + (bm + srow) * 512 + sc;
    const float* Bg = Bw + (bn + srow) * 512 + sc;
    uint32_t smem_base = (uint32_t)__cvta_generic_to_shared(sm);

    float acc[4][8][4];
    #pragma unroll
    for (int i = 0; i < 4; i++)
        #pragma unroll
        for (int j = 0; j < 8; j++)
            #pragma unroll
            for (int r = 0; r < 4; r++) acc[i][j][r] = 0.f;

    // stage kt=0
    {
        uint32_t ad = smem_base + (uint32_t)(srow*ASTR + sc)*4u;
        uint32_t bd = smem_base + (uint32_t)(ABUF + srow*ASTR + sc)*4u;
        #pragma unroll
        for (int i = 0; i < 4; i++) cpasync16(ad + i*32*ASTR*4, Ag + i*32*512);
        #pragma unroll
        for (int i = 0; i < 8; i++) cpasync16(bd + i*32*ASTR*4, Bg + i*32*512);
        asm volatile("cp.async.commit_group;");
    }

    for (int kt = 0; kt < 16; kt++) {
        if (kt + 1 < 16) {
            int buf = (kt + 1) & 1;
            uint32_t ad = smem_base + (uint32_t)(buf*STG + srow*ASTR + sc)*4u;
            uint32_t bd = smem_base + (uint32_t)(buf*STG + ABUF + srow*ASTR + sc)*4u;
            const float* ag = Ag + (kt+1)*32;
            const float* bg = Bg + (kt+1)*32;
            #pragma unroll
            for (int i = 0; i < 4; i++) cpasync16(ad + i*32*ASTR*4, ag + i*32*512);
            #pragma unroll
            for (int i = 0; i < 8; i++) cpasync16(bd + i*32*ASTR*4, bg + i*32*512);
            asm volatile("cp.async.commit_group;");
            asm volatile("cp.async.wait_group 1;");
        } else {
            asm volatile("cp.async.wait_group 0;");
        }
        __syncthreads();
        const float* Ab = sm + (kt & 1)*STG;
        const float* Bb = Ab + ABUF;

        #pragma unroll
        for (int ks = 0; ks < 4; ks++) {
            int ar = wm*64 + (lane >> 2);
            int ck = ks*8 + (lane & 3);
            uint32_t ah[4][4], al[4][4];
            #pragma unroll
            for (int mt = 0; mt < 4; mt++) {
                int base = (ar + mt*16)*ASTR + ck;
                float v0 = Ab[base], v1 = Ab[base + 8*ASTR];
                float v2 = Ab[base + 4], v3 = Ab[base + 8*ASTR + 4];
                ah[mt][0] = cvt_tf32(v0); al[mt][0] = __float_as_uint(v0 - __uint_as_float(ah[mt][0]));
                ah[mt][1] = cvt_tf32(v1); al[mt][1] = __float_as_uint(v1 - __uint_as_float(ah[mt][1]));
                ah[mt][2] = cvt_tf32(v2); al[mt][2] = __float_as_uint(v2 - __uint_as_float(ah[mt][2]));
                ah[mt][3] = cvt_tf32(v3); al[mt][3] = __float_as_uint(v3 - __uint_as_float(ah[mt][3]));
            }
            int br = wn*64 + (lane >> 2);
            #pragma unroll
            for (int half = 0; half < 2; half++) {
                uint32_t bh[4][2], bl[4][2];
                #pragma unroll
                for (int j = 0; j < 4; j++) {
                    int nt = half*4 + j;
                    int base = (br + nt*8)*ASTR + ck;
                    float v0 = Bb[base], v1 = Bb[base + 4];
                    bh[j][0] = cvt_tf32(v0); bl[j][0] = __float_as_uint(v0 - __uint_as_float(bh[j][0]));
                    bh[j][1] = cvt_tf32(v1); bl[j][1] = __float_as_uint(v1 - __uint_as_float(bh[j][1]));
                }
                #pragma unroll
                for (int mt = 0; mt < 4; mt++)
                    #pragma unroll
                    for (int j = 0; j < 4; j++) {
                        float* c = acc[mt][half*4 + j];
                        mma8(c[0], c[1], c[2], c[3], ah[mt][0], ah[mt][1], ah[mt][2], ah[mt][3], bh[j][0], bh[j][1]);
                        mma8(c[0], c[1], c[2], c[3], ah[mt][0], ah[mt][1], ah[mt][2], ah[mt][3], bl[j][0], bl[j][1]);
                        mma8(c[0], c[1], c[2], c[3], al[mt][0], al[mt][1], al[mt][2], al[mt][3], bh[j][0], bh[j][1]);
                    }
            }
        }
        __syncthreads();
    }

    #pragma unroll
    for (int mt = 0; mt < 4; mt++) {
        size_t r0 = bm + wm*64 + mt*16 + (lane >> 2);
        #pragma unroll
        for (int nt = 0; nt < 8; nt++) {
            size_t c0 = bn + wn*64 + nt*8 + (lane & 3)*2;
            float b0 = bias ? bias[c0] : 0.f;
            float b1 = bias ? bias[c0 + 1] : 0.f;
            *(float2*)&C[r0*(size_t)N + c0] =
                make_float2(acc[mt][nt][0] + b0, acc[mt][nt][1] + b1);
            *(float2*)&C[(r0 + 8)*(size_t)N + c0] =
                make_float2(acc[mt][nt][2] + b0, acc[mt][nt][3] + b1);
        }
    }
}

// ---------------- fused persistent LSTM: 1 barrier per segment ----------------
// segment s: L0(t=s) [s<T] and L1(t=s-1) [s>=1]; both read g_h0[s&1].
__global__ __launch_bounds__(256,1) void k_lstm(const float* __restrict__ init_h,
                                                const float* __restrict__ init_c,
                                                const float* __restrict__ W_ih,
                                                const float* __restrict__ W_hh) {
    __shared__ float4 sredA[128];
    __shared__ float4 sredB[128];
    int tid = threadIdx.x, lane = tid & 31, wid = tid >> 5;
    int hout  = blockIdx.x*4 + (wid & 3);
    int khalf = wid >> 2;

    for (int i = blockIdx.x*256 + tid; i < BB*HH; i += gridDim.x*256) {
        int b = i >> 9, h = i & 511;
        g_h0[0][i] = init_h[b*1024 + h];
        g_h1[0][i] = init_h[b*1024 + 512 + h];
        g_c0[i]    = init_c[b*1024 + h];
        g_c1[i]    = init_c[b*1024 + 512 + h];
    }
    gbar();

    const float* W0  = W_hh + (size_t)hout*HH;                 // layer0 Whh
    const float* Wi1 = W_ih + 1048576 + (size_t)hout*HH;       // layer1 Wih
    const float* Wh1 = W_hh + 1048576 + (size_t)hout*HH;       // layer1 Whh

    for (int s = 0; s <= TT; s++) {
        int p0 = s & 1;
        bool doL0 = (s < TT), doL1 = (s >= 1);
        float s0 = doL0 ? 0.5f : 0.0f;   // fold ALPHA mix scale into weights
        float s1 = doL1 ? 1.0f : 0.0f;
        float sh = doL1 ? 0.5f : 0.0f;
        const float* h0p = g_h0[p0];
        const float* h1p = g_h1[doL1 ? ((s - 1) & 1) : 0];

        float accA[4][16], accB[4][16];
        #pragma unroll
        for (int c = 0; c < 4; c++)
            #pragma unroll
            for (int b = 0; b < 16; b++) { accA[c][b] = 0.f; accB[c][b] = 0.f; }

        #pragma unroll 2
        for (int kk = 0; kk < 8; kk++) {
            int k = khalf*256 + kk*32 + lane;
            float w0 = s0*W0[k],         w1 = s0*W0[262144+k];
            float w2 = s0*W0[524288+k],  w3 = s0*W0[786432+k];
            float u0 = s1*Wi1[k],        u1 = s1*Wi1[262144+k];
            float u2 = s1*Wi1[524288+k], u3 = s1*Wi1[786432+k];
            #pragma unroll
            for (int b = 0; b < 16; b++) {
                float xv = h0p[b*HH + k];
                accA[0][b] = fmaf(w0, xv, accA[0][b]);
                accA[1][b] = fmaf(w1, xv, accA[1][b]);
                accA[2][b] = fmaf(w2, xv, accA[2][b]);
                accA[3][b] = fmaf(w3, xv, accA[3][b]);
                accB[0][b] = fmaf(u0, xv, accB[0][b]);
                accB[1][b] = fmaf(u1, xv, accB[1][b]);
                accB[2][b] = fmaf(u2, xv, accB[2][b]);
                accB[3][b] = fmaf(u3, xv, accB[3][b]);
            }
        }
        #pragma unroll 2
        for (int kk = 0; kk < 8; kk++) {
            int k = khalf*256 + kk*32 + lane;
            float v0 = sh*Wh1[k],        v1 = sh*Wh1[262144+k];
            float v2 = sh*Wh1[524288+k], v3 = sh*Wh1[786432+k];
            #pragma unroll
            for (int b = 0; b < 16; b++) {
                float hv = h1p[b*HH + k];
                accB[0][b] = fmaf(v0, hv, accB[0][b]);
                accB[1][b] = fmaf(v1, hv, accB[1][b]);
                accB[2][b] = fmaf(v2, hv, accB[2][b]);
                accB[3][b] = fmaf(v3, hv, accB[3][b]);
            }
        }
        #pragma unroll
        for (int c = 0; c < 4; c++)
            #pragma unroll
            for (int b = 0; b < 16; b++)
                #pragma unroll
                for (int o = 16; o > 0; o >>= 1) {
                    accA[c][b] += __shfl_xor_sync(0xffffffffu, accA[c][b], o);
                    accB[c][b] += __shfl_xor_sync(0xffffffffu, accB[c][b], o);
                }
        {
            float a0=0,a1=0,a2=0,a3=0, b0v=0,b1v=0,b2v=0,b3v=0;
            #pragma unroll
            for (int b = 0; b < 16; b++)
                if (lane == b) {
                    a0=accA[0][b]; a1=accA[1][b]; a2=accA[2][b]; a3=accA[3][b];
                    b0v=accB[0][b]; b1v=accB[1][b]; b2v=accB[2][b]; b3v=accB[3][b];
                }
            if (lane < 16) {
                sredA[wid*16 + lane] = make_float4(a0,a1,a2,a3);
                sredB[wid*16 + lane] = make_float4(b0v,b1v,b2v,b3v);
            }
        }
        __syncthreads();
        if (wid < 4 && lane < 16) {
            int b = lane;
            int si = b*HH + hout;
            if (doL0) {
                float4 pa = sredA[wid*16 + b], pb = sredA[(wid+4)*16 + b];
                const float* Kp = g_K + b*G4;
                const float* gx = g_gx0 + ((size_t)(b*TT + s))*G4;
                float iv = pa.x+pb.x + Kp[hout]      + gx[hout];
                float fv = pa.y+pb.y + Kp[hout+512]  + gx[hout+512];
                float gv = pa.z+pb.z + Kp[hout+1024] + gx[hout+1024];
                float ov = pa.w+pb.w + Kp[hout+1536] + gx[hout+1536];
                float cn = sigf(fv)*g_c0[si] + sigf(iv)*tanhf(gv);
                g_c0[si] = cn;
                g_h0[p0^1][si] = sigf(ov)*tanhf(cn);
            }
            if (doL1) {
                float4 pa = sredB[wid*16 + b], pb = sredB[(wid+4)*16 + b];
                const float* Kp = g_K + 32768 + b*G4;
                float iv = pa.x+pb.x + Kp[hout];
                float fv = pa.y+pb.y + Kp[hout+512];
                float gv = pa.z+pb.z + Kp[hout+1024];
                float ov = pa.w+pb.w + Kp[hout+1536];
                float cn = sigf(fv)*g_c1[si] + sigf(iv)*tanhf(gv);
                g_c1[si] = cn;
                float hn = sigf(ov)*tanhf(cn);
                g_h1[s & 1][si] = hn;
                g_X[((size_t)(b*TT + (s-1)))*HH + hout] = hn;
            }
        }
        gbar();
    }
}

// ---------------- per-row max + argmax over V ----------------
__global__ void k_argmax(const float* __restrict__ logits) {
    __shared__ float sm[256];
    __shared__ int   si[256];
    int r = blockIdx.x, tid = threadIdx.x;
    const float* row = logits + (size_t)r*VV;
    float bm = -1e30f; int bi = 0;
    for (int j = tid; j < VV; j += 256) {
        float v = row[j];
        if (v > bm || (v == bm && j < bi)) { bm = v; bi = j; }
    }
    sm[tid] = bm; si[tid] = bi;
    __syncthreads();
    for (int s = 128; s > 0; s >>= 1) {
        if (tid < s) {
            float v = sm[tid+s]; int i2 = si[tid+s];
            if (v > sm[tid] || (v == sm[tid] && i2 < si[tid])) { sm[tid] = v; si[tid] = i2; }
        }
        __syncthreads();
    }
    if (tid == 0) { g_rowmax[r] = sm[0]; g_argidx[r] = si[0]; }
}

// ---------------- sequential EOS scan + ids output ----------------
__global__ void k_eos(float* __restrict__ ids_out) {
    int b = threadIdx.x;
    if (b >= BB) return;
    int eos = 0;
    for (int t = 0; t < TT; t++) {
        int r = b*TT + t;
        int id = g_argidx[r];
        if (eos) { g_mask[r] = 1; id = PAD_ID; }
        else       g_mask[r] = 0;
        if (ids_out) ids_out[r] = (float)id;
        if (id == EOS_ID) eos = 1;
    }
}

// ---------------- in-place softmax / one-hot masking ----------------
__global__ void k_softmax(float* __restrict__ probs) {
    __shared__ float ss[256];
    int r = blockIdx.x, tid = threadIdx.x;
    float* row = probs + (size_t)r*VV;
    if (g_mask[r]) {
        float4 z = make_float4(0.f,0.f,0.f,0.f);
        for (int j4 = tid; j4 < VV/4; j4 += 256) ((float4*)row)[j4] = z;
        if (tid == 0) row[PAD_ID] = 1.0f;
        return;
    }
    float m = g_rowmax[r];
    float s = 0.f;
    for (int j4 = tid; j4 < VV/4; j4 += 256) {
        float4 v = ((float4*)row)[j4];
        s += __expf(v.x-m) + __expf(v.y-m) + __expf(v.z-m) + __expf(v.w-m);
    }
    ss[tid] = s;
    __syncthreads();
    for (int st = 128; st > 0; st >>= 1) {
        if (tid < st) ss[tid] += ss[tid+st];
        __syncthreads();
    }
    float inv = 1.0f / ss[0];
    for (int j4 = tid; j4 < VV/4; j4 += 256) {
        float4 v = ((float4*)row)[j4];
        v.x = __expf(v.x-m)*inv; v.y = __expf(v.y-m)*inv;
        v.z = __expf(v.z-m)*inv; v.w = __expf(v.w-m)*inv;
        ((float4*)row)[j4] = v;
    }
}

extern "C" void kernel_launch(void* const* d_in, const int* in_sizes, int n_in,
                              void* d_out, int out_size) {
    const float* init_h  = (const float*)d_in[0];
    const float* init_c  = (const float*)d_in[1];
    const int*   init_in = (const int*)d_in[2];
    const int*   targets = (const int*)d_in[3];
    const float* emb     = (const float*)d_in[4];
    const float* embW    = (const float*)d_in[5];
    const float* W_ih    = (const float*)d_in[6];
    const float* W_hh    = (const float*)d_in[7];
    const float* b_ih    = (const float*)d_in[8];
    const float* b_hh    = (const float*)d_in[9];
    const float* W_out   = (const float*)d_in[10];
    const float* b_out   = (const float*)d_in[11];
    const float* aW1     = (const float*)d_in[12];
    const float* ab1     = (const float*)d_in[13];
    const float* aW2     = (const float*)d_in[14];
    const float* ab2     = (const float*)d_in[15];
    float* out = (float*)d_out;
    float* ids_out = ((size_t)out_size >= BTV + (size_t)NROW) ? out + BTV : nullptr;

    static bool attr_done = false;
    if (!attr_done) {
        cudaFuncSetAttribute(k_mma_nt, cudaFuncAttributeMaxDynamicSharedMemorySize,
                             2*STG*(int)sizeof(float));
        attr_done = true;
    }
    float *Xep = nullptr, *gx0p = nullptr, *Xp = nullptr;
    cudaGetSymbolAddress((void**)&Xep,  g_Xe);
    cudaGetSymbolAddress((void**)&gx0p, g_gx0);
    cudaGetSymbolAddress((void**)&Xp,   g_X);

    k_attn_scores<<<BB*DD*LL, AH>>>(emb, aW1, ab1, aW2, ab2);
    k_attn_ctx<<<BB*LL, 256>>>(emb);
    k_ctx_gates<<<(LL*BB*G4)/8, 256>>>(W_hh, b_ih, b_hh);
    k_embed<<<(BB*TT*HH/4 + 255)/256, 256>>>(init_in, targets, embW);
    k_mma_nt<<<dim3(G4/256, NROW/128), 256, 2*STG*sizeof(float)>>>(
        Xep, W_ih, nullptr, gx0p, G4);
    k_lstm<<<128, 256>>>(init_h, init_c, W_ih, W_hh);
    k_mma_nt<<<dim3(VV/256, NROW/128), 256, 2*STG*sizeof(float)>>>(
        Xp, W_out, b_out, out, VV);
    k_argmax<<<NROW, 256>>>(out);
    k_eos<<<1, 32>>>(ids_out);
    k_softmax<<<NROW, 256>>>(out);
}

// round 8
// speedup vs baseline: 1.1448x; 1.1448x over previous
#include <cuda_runtime.h>
#include <cuda_bf16.h>
#include <cstdint>

#define BB   16
#define TT   128
#define VV   32000
#define HH   512
#define LL   2
#define DD   8
#define AH   256
#define G4   2048
#define PAD_ID 0
#define EOS_ID 3
#define NROW (BB*TT)            // 2048
#define BTV  ((size_t)NROW*VV)

// ---------------- device scratch ----------------
__device__ float g_scores[BB*DD*LL];
__device__ float g_ctx[BB*LL*HH];
__device__ float g_K[LL*BB*G4];
__device__ float g_Xe[NROW*HH];
__device__ float g_gx0[(size_t)NROW*G4];
__device__ float g_X[NROW*HH];
__device__ float g_h0[2][BB*HH];
__device__ float g_h1[2][BB*HH];
__device__ float g_c0[BB*HH];
__device__ float g_c1[BB*HH];
__device__ float g_rowmax[NROW];
__device__ int   g_argidx[NROW];
__device__ int   g_mask[NROW];
__device__ unsigned g_bcnt = 0;
__device__ unsigned g_bgen = 0;
// bf16 split scratch (weights + activations)
__device__ __nv_bfloat16 g_Whi[(size_t)VV*HH];
__device__ __nv_bfloat16 g_Wlo[(size_t)VV*HH];
__device__ __nv_bfloat16 g_Ahi[NROW*HH];
__device__ __nv_bfloat16 g_Alo[NROW*HH];

__device__ __forceinline__ float sigf(float x){ return 1.0f/(1.0f+__expf(-x)); }

// grid barrier (all CTAs resident)
__device__ __forceinline__ void gbar() {
    __threadfence();
    __syncthreads();
    if (threadIdx.x == 0) {
        volatile unsigned* vg = &g_bgen;
        unsigned g = *vg;
        unsigned a = atomicAdd(&g_bcnt, 1u);
        if (a == gridDim.x - 1u) {
            g_bcnt = 0;
            __threadfence();
            atomicAdd(&g_bgen, 1u);
        } else {
            while (*vg == g) { __nanosleep(64); }
        }
        __threadfence();
    }
    __syncthreads();
}

// ---------------- K1: attention scores  blk=(b*D+d)*L+l ----------------
__global__ void k_attn_scores(const float* __restrict__ emb, const float* __restrict__ W1,
                              const float* __restrict__ b1, const float* __restrict__ W2,
                              const float* __restrict__ b2) {
    __shared__ float se[HH];
    __shared__ float red[AH];
    int blk = blockIdx.x;
    const float* ep = emb + (size_t)blk * HH;
    for (int i = threadIdx.x; i < HH; i += AH) se[i] = ep[i];
    __syncthreads();
    int a = threadIdx.x;
    const float* w1 = W1 + (size_t)a * HH;
    float dot = 0.f;
    #pragma unroll 8
    for (int k = 0; k < HH; k++) dot += se[k] * w1[k];
    red[a] = tanhf(dot + b1[a]) * W2[a];
    __syncthreads();
    for (int s = AH/2; s > 0; s >>= 1) {
        if (a < s) red[a] += red[a + s];
        __syncthreads();
    }
    if (a == 0) g_scores[blk] = red[0] + b2[0];
}

// ---------------- K2: softmax over docs + context ----------------
__global__ void k_attn_ctx(const float* __restrict__ emb) {
    int b = blockIdx.x >> 1, l = blockIdx.x & 1;
    __shared__ float s[DD];
    if (threadIdx.x < DD) s[threadIdx.x] = g_scores[(b*DD + threadIdx.x)*LL + l];
    __syncthreads();
    float mx = -1e30f;
    #pragma unroll
    for (int d = 0; d < DD; d++) mx = fmaxf(mx, s[d]);
    float w[DD]; float sum = 0.f;
    #pragma unroll
    for (int d = 0; d < DD; d++) { w[d] = __expf(s[d] - mx); sum += w[d]; }
    float inv = 1.0f / sum;
    for (int h = threadIdx.x; h < HH; h += 256) {
        float acc = 0.f;
        #pragma unroll
        for (int d = 0; d < DD; d++)
            acc += w[d] * inv * emb[((size_t)(b*DD + d)*LL + l)*HH + h];
        g_ctx[(b*LL + l)*HH + h] = acc;
    }
}

// ---------------- K3: K[l][b][g] = 0.5*ctx@Whh^T + b_ih + b_hh ----------------
__global__ void k_ctx_gates(const float* __restrict__ Whh, const float* __restrict__ bih,
                            const float* __restrict__ bhh) {
    int out  = blockIdx.x * 8 + (threadIdx.x >> 5);
    int lane = threadIdx.x & 31;
    int l = out >> 15;
    int b = (out >> 11) & 15;
    int g = out & 2047;
    const float* wr = Whh + (size_t)l*G4*HH + (size_t)g*HH;
    const float* cx = g_ctx + (b*LL + l)*HH;
    float acc = 0.f;
    for (int k = lane; k < HH; k += 32) acc += wr[k]*cx[k];
    #pragma unroll
    for (int o = 16; o > 0; o >>= 1) acc += __shfl_xor_sync(0xffffffffu, acc, o);
    if (lane == 0) g_K[out] = 0.5f*acc + bih[l*G4 + g] + bhh[l*G4 + g];
}

// ---------------- K4: embedding gather ----------------
__global__ void k_embed(const int* __restrict__ init_input, const int* __restrict__ targets,
                        const float* __restrict__ embW) {
    int i4 = blockIdx.x * 256 + threadIdx.x;       // over B*T*H/4
    if (i4 >= BB*TT*HH/4) return;
    int r  = i4 >> 7;
    int h4 = i4 & 127;
    int b = r >> 7, t = r & 127;
    int tok = (t == 0) ? init_input[b] : targets[b*TT + t - 1];
    ((float4*)g_Xe)[i4] = ((const float4*)(embW + (size_t)tok*HH))[h4];
}

// ---------------- bf16 hi/lo split: hi=rn(v), lo=rn(v-hi) ----------------
__global__ void k_split(const float* __restrict__ src, __nv_bfloat16* __restrict__ hi,
                        __nv_bfloat16* __restrict__ lo, int n4) {
    int i = blockIdx.x*256 + threadIdx.x;
    if (i >= n4) return;
    float4 v = ((const float4*)src)[i];
    __nv_bfloat16 h0 = __float2bfloat16_rn(v.x);
    __nv_bfloat16 h1 = __float2bfloat16_rn(v.y);
    __nv_bfloat16 h2 = __float2bfloat16_rn(v.z);
    __nv_bfloat16 h3 = __float2bfloat16_rn(v.w);
    __nv_bfloat16 l0 = __float2bfloat16_rn(v.x - __bfloat162float(h0));
    __nv_bfloat16 l1 = __float2bfloat16_rn(v.y - __bfloat162float(h1));
    __nv_bfloat16 l2 = __float2bfloat16_rn(v.z - __bfloat162float(h2));
    __nv_bfloat16 l3 = __float2bfloat16_rn(v.w - __bfloat162float(h3));
    __nv_bfloat162* H = (__nv_bfloat162*)hi;
    __nv_bfloat162* L = (__nv_bfloat162*)lo;
    __nv_bfloat162 a; a.x = h0; a.y = h1;
    __nv_bfloat162 b; b.x = h2; b.y = h3;
    __nv_bfloat162 c; c.x = l0; c.y = l1;
    __nv_bfloat162 d; d.x = l2; d.y = l3;
    H[2*i] = a; H[2*i+1] = b;
    L[2*i] = c; L[2*i+1] = d;
}

// ================= bf16x3-split mma.sync GEMM (NT) =================
// C[M x N] = A[M x 512] * B[N x 512]^T (+bias), near-fp32 accuracy.
// CTA tile 128x256, BK=32, 8 warps (2 M x 4 N), warp tile 64x64, m16n8k16.
__device__ __forceinline__ void mma16(float* c, const uint32_t* a,
                                      uint32_t b0, uint32_t b1) {
    asm volatile("mma.sync.aligned.m16n8k16.row.col.f32.bf16.bf16.f32 "
        "{%0,%1,%2,%3}, {%4,%5,%6,%7}, {%8,%9}, {%0,%1,%2,%3};"
        : "+f"(c[0]), "+f"(c[1]), "+f"(c[2]), "+f"(c[3])
        : "r"(a[0]), "r"(a[1]), "r"(a[2]), "r"(a[3]), "r"(b0), "r"(b1));
}
__device__ __forceinline__ void cpasync16(uint32_t s, const void* g) {
    asm volatile("cp.async.ca.shared.global [%0], [%1], 16;" :: "r"(s), "l"(g));
}

#define SA    40                 // padded row stride (bf16 elems) -> conflict-free
#define AHI_E 0
#define ALO_E (128*SA)           // 5120
#define BHI_E (2*128*SA)         // 10240
#define BLO_E (BHI_E + 256*SA)   // 20480
#define STG_E (BLO_E + 256*SA)   // 30720 elems per stage
#define GEMM_SMEM (2*STG_E*2)    // 122880 bytes

__global__ __launch_bounds__(256) void k_bf16_gemm(
        const __nv_bfloat16* __restrict__ Ahi, const __nv_bfloat16* __restrict__ Alo,
        const __nv_bfloat16* __restrict__ Bhi, const __nv_bfloat16* __restrict__ Blo,
        const float* __restrict__ bias, float* __restrict__ C, int N) {
    extern __shared__ __nv_bfloat16 smb[];
    uint32_t sb = (uint32_t)__cvta_generic_to_shared(smb);
    int tid = threadIdx.x, lane = tid & 31, wid = tid >> 5;
    int wm = wid & 1, wn = wid >> 1;
    size_t bm = (size_t)blockIdx.y * 128;
    size_t bn = (size_t)blockIdx.x * 256;

    float acc[4][8][4];
    #pragma unroll
    for (int i = 0; i < 4; i++)
        #pragma unroll
        for (int j = 0; j < 8; j++)
            #pragma unroll
            for (int r = 0; r < 4; r++) acc[i][j][r] = 0.f;

    #define LOAD_STAGE(st) do { \
        uint32_t b_ = sb + (uint32_t)(((st) & 1) * (STG_E*2)); \
        int kc_ = (st) * 32; \
        _Pragma("unroll") \
        for (int j_ = 0; j_ < 2; j_++) { \
            int cid_ = tid + 256*j_; \
            int r_ = cid_ >> 2, ch_ = (cid_ & 3) * 8; \
            cpasync16(b_ + (uint32_t)(r_*SA + ch_)*2u, Ahi + (bm + r_)*512 + kc_ + ch_); \
            cpasync16(b_ + (uint32_t)(ALO_E + r_*SA + ch_)*2u, Alo + (bm + r_)*512 + kc_ + ch_); \
        } \
        _Pragma("unroll") \
        for (int j_ = 0; j_ < 4; j_++) { \
            int cid_ = tid + 256*j_; \
            int r_ = cid_ >> 2, ch_ = (cid_ & 3) * 8; \
            cpasync16(b_ + (uint32_t)(BHI_E + r_*SA + ch_)*2u, Bhi + (bn + r_)*512 + kc_ + ch_); \
            cpasync16(b_ + (uint32_t)(BLO_E + r_*SA + ch_)*2u, Blo + (bn + r_)*512 + kc_ + ch_); \
        } \
        asm volatile("cp.async.commit_group;"); \
    } while(0)

    LOAD_STAGE(0);

    for (int s = 0; s < 16; s++) {
        if (s + 1 < 16) {
            LOAD_STAGE(s + 1);
            asm volatile("cp.async.wait_group 1;");
        } else {
            asm volatile("cp.async.wait_group 0;");
        }
        __syncthreads();
        const __nv_bfloat16* Sb = smb + (s & 1) * STG_E;

        #pragma unroll
        for (int ks = 0; ks < 2; ks++) {
            int kc = ks*16 + (lane & 3)*2;
            uint32_t ah[4][4], al[4][4];
            #pragma unroll
            for (int mt = 0; mt < 4; mt++) {
                int r = wm*64 + mt*16 + (lane >> 2);
                const __nv_bfloat16* pa = Sb + AHI_E + r*SA + kc;
                const __nv_bfloat16* qa = Sb + ALO_E + r*SA + kc;
                ah[mt][0] = *(const uint32_t*)pa;
                ah[mt][1] = *(const uint32_t*)(pa + 8*SA);
                ah[mt][2] = *(const uint32_t*)(pa + 8);
                ah[mt][3] = *(const uint32_t*)(pa + 8*SA + 8);
                al[mt][0] = *(const uint32_t*)qa;
                al[mt][1] = *(const uint32_t*)(qa + 8*SA);
                al[mt][2] = *(const uint32_t*)(qa + 8);
                al[mt][3] = *(const uint32_t*)(qa + 8*SA + 8);
            }
            #pragma unroll
            for (int nt = 0; nt < 8; nt++) {
                int c = wn*64 + nt*8 + (lane >> 2);
                const __nv_bfloat16* pb = Sb + BHI_E + c*SA + kc;
                const __nv_bfloat16* qb = Sb + BLO_E + c*SA + kc;
                uint32_t bh0 = *(const uint32_t*)pb, bh1 = *(const uint32_t*)(pb + 8);
                uint32_t bl0 = *(const uint32_t*)qb, bl1 = *(const uint32_t*)(qb + 8);
                #pragma unroll
                for (int mt = 0; mt < 4; mt++) {
                    float* cc = acc[mt][nt];
                    mma16(cc, ah[mt], bh0, bh1);
                    mma16(cc, ah[mt], bl0, bl1);
                    mma16(cc, al[mt], bh0, bh1);
                }
            }
        }
        __syncthreads();
    }

    #pragma unroll
    for (int mt = 0; mt < 4; mt++) {
        size_t r0 = bm + wm*64 + mt*16 + (lane >> 2);
        #pragma unroll
        for (int nt = 0; nt < 8; nt++) {
            size_t c0 = bn + wn*64 + nt*8 + (lane & 3)*2;
            float b0 = bias ? bias[c0] : 0.f;
            float b1 = bias ? bias[c0 + 1] : 0.f;
            *(float2*)&C[r0*(size_t)N + c0] =
                make_float2(acc[mt][nt][0] + b0, acc[mt][nt][1] + b1);
            *(float2*)&C[(r0 + 8)*(size_t)N + c0] =
                make_float2(acc[mt][nt][2] + b0, acc[mt][nt][3] + b1);
        }
    }
    #undef LOAD_STAGE
}

// ---------------- fused persistent LSTM: 1 barrier per segment ----------------
// segment s: L0(t=s) [s<T] and L1(t=s-1) [s>=1]; both read g_h0[s&1].
__global__ __launch_bounds__(256,1) void k_lstm(const float* __restrict__ init_h,
                                                const float* __restrict__ init_c,
                                                const float* __restrict__ W_ih,
                                                const float* __restrict__ W_hh) {
    __shared__ float4 sredA[128];
    __shared__ float4 sredB[128];
    int tid = threadIdx.x, lane = tid & 31, wid = tid >> 5;
    int hout  = blockIdx.x*4 + (wid & 3);
    int khalf = wid >> 2;

    for (int i = blockIdx.x*256 + tid; i < BB*HH; i += gridDim.x*256) {
        int b = i >> 9, h = i & 511;
        g_h0[0][i] = init_h[b*1024 + h];
        g_h1[0][i] = init_h[b*1024 + 512 + h];
        g_c0[i]    = init_c[b*1024 + h];
        g_c1[i]    = init_c[b*1024 + 512 + h];
    }
    gbar();

    const float* W0  = W_hh + (size_t)hout*HH;
    const float* Wi1 = W_ih + 1048576 + (size_t)hout*HH;
    const float* Wh1 = W_hh + 1048576 + (size_t)hout*HH;

    for (int s = 0; s <= TT; s++) {
        int p0 = s & 1;
        bool doL0 = (s < TT), doL1 = (s >= 1);
        float s0 = doL0 ? 0.5f : 0.0f;
        float s1 = doL1 ? 1.0f : 0.0f;
        float sh = doL1 ? 0.5f : 0.0f;
        const float* h0p = g_h0[p0];
        const float* h1p = g_h1[doL1 ? ((s - 1) & 1) : 0];

        float accA[4][16], accB[4][16];
        #pragma unroll
        for (int c = 0; c < 4; c++)
            #pragma unroll
            for (int b = 0; b < 16; b++) { accA[c][b] = 0.f; accB[c][b] = 0.f; }

        #pragma unroll 2
        for (int kk = 0; kk < 8; kk++) {
            int k = khalf*256 + kk*32 + lane;
            float w0 = s0*W0[k],         w1 = s0*W0[262144+k];
            float w2 = s0*W0[524288+k],  w3 = s0*W0[786432+k];
            float u0 = s1*Wi1[k],        u1 = s1*Wi1[262144+k];
            float u2 = s1*Wi1[524288+k], u3 = s1*Wi1[786432+k];
            #pragma unroll
            for (int b = 0; b < 16; b++) {
                float xv = h0p[b*HH + k];
                accA[0][b] = fmaf(w0, xv, accA[0][b]);
                accA[1][b] = fmaf(w1, xv, accA[1][b]);
                accA[2][b] = fmaf(w2, xv, accA[2][b]);
                accA[3][b] = fmaf(w3, xv, accA[3][b]);
                accB[0][b] = fmaf(u0, xv, accB[0][b]);
                accB[1][b] = fmaf(u1, xv, accB[1][b]);
                accB[2][b] = fmaf(u2, xv, accB[2][b]);
                accB[3][b] = fmaf(u3, xv, accB[3][b]);
            }
        }
        #pragma unroll 2
        for (int kk = 0; kk < 8; kk++) {
            int k = khalf*256 + kk*32 + lane;
            float v0 = sh*Wh1[k],        v1 = sh*Wh1[262144+k];
            float v2 = sh*Wh1[524288+k], v3 = sh*Wh1[786432+k];
            #pragma unroll
            for (int b = 0; b < 16; b++) {
                float hv = h1p[b*HH + k];
                accB[0][b] = fmaf(v0, hv, accB[0][b]);
                accB[1][b] = fmaf(v1, hv, accB[1][b]);
                accB[2][b] = fmaf(v2, hv, accB[2][b]);
                accB[3][b] = fmaf(v3, hv, accB[3][b]);
            }
        }
        #pragma unroll
        for (int c = 0; c < 4; c++)
            #pragma unroll
            for (int b = 0; b < 16; b++)
                #pragma unroll
                for (int o = 16; o > 0; o >>= 1) {
                    accA[c][b] += __shfl_xor_sync(0xffffffffu, accA[c][b], o);
                    accB[c][b] += __shfl_xor_sync(0xffffffffu, accB[c][b], o);
                }
        {
            float a0=0,a1=0,a2=0,a3=0, b0v=0,b1v=0,b2v=0,b3v=0;
            #pragma unroll
            for (int b = 0; b < 16; b++)
                if (lane == b) {
                    a0=accA[0][b]; a1=accA[1][b]; a2=accA[2][b]; a3=accA[3][b];
                    b0v=accB[0][b]; b1v=accB[1][b]; b2v=accB[2][b]; b3v=accB[3][b];
                }
            if (lane < 16) {
                sredA[wid*16 + lane] = make_float4(a0,a1,a2,a3);
                sredB[wid*16 + lane] = make_float4(b0v,b1v,b2v,b3v);
            }
        }
        __syncthreads();
        if (wid < 4 && lane < 16) {
            int b = lane;
            int si = b*HH + hout;
            if (doL0) {
                float4 pa = sredA[wid*16 + b], pb = sredA[(wid+4)*16 + b];
                const float* Kp = g_K + b*G4;
                const float* gx = g_gx0 + ((size_t)(b*TT + s))*G4;
                float iv = pa.x+pb.x + Kp[hout]      + gx[hout];
                float fv = pa.y+pb.y + Kp[hout+512]  + gx[hout+512];
                float gv = pa.z+pb.z + Kp[hout+1024] + gx[hout+1024];
                float ov = pa.w+pb.w + Kp[hout+1536] + gx[hout+1536];
                float cn = sigf(fv)*g_c0[si] + sigf(iv)*tanhf(gv);
                g_c0[si] = cn;
                g_h0[p0^1][si] = sigf(ov)*tanhf(cn);
            }
            if (doL1) {
                float4 pa = sredB[wid*16 + b], pb = sredB[(wid+4)*16 + b];
                const float* Kp = g_K + 32768 + b*G4;
                float iv = pa.x+pb.x + Kp[hout];
                float fv = pa.y+pb.y + Kp[hout+512];
                float gv = pa.z+pb.z + Kp[hout+1024];
                float ov = pa.w+pb.w + Kp[hout+1536];
                float cn = sigf(fv)*g_c1[si] + sigf(iv)*tanhf(gv);
                g_c1[si] = cn;
                float hn = sigf(ov)*tanhf(cn);
                g_h1[s & 1][si] = hn;
                g_X[((size_t)(b*TT + (s-1)))*HH + hout] = hn;
            }
        }
        gbar();
    }
}

// ---------------- per-row max + argmax over V ----------------
__global__ void k_argmax(const float* __restrict__ logits) {
    __shared__ float sm[256];
    __shared__ int   si[256];
    int r = blockIdx.x, tid = threadIdx.x;
    const float* row = logits + (size_t)r*VV;
    float bm = -1e30f; int bi = 0;
    for (int j = tid; j < VV; j += 256) {
        float v = row[j];
        if (v > bm || (v == bm && j < bi)) { bm = v; bi = j; }
    }
    sm[tid] = bm; si[tid] = bi;
    __syncthreads();
    for (int s = 128; s > 0; s >>= 1) {
        if (tid < s) {
            float v = sm[tid+s]; int i2 = si[tid+s];
            if (v > sm[tid] || (v == sm[tid] && i2 < si[tid])) { sm[tid] = v; si[tid] = i2; }
        }
        __syncthreads();
    }
    if (tid == 0) { g_rowmax[r] = sm[0]; g_argidx[r] = si[0]; }
}

// ---------------- sequential EOS scan + ids output ----------------
__global__ void k_eos(float* __restrict__ ids_out) {
    int b = threadIdx.x;
    if (b >= BB) return;
    int eos = 0;
    for (int t = 0; t < TT; t++) {
        int r = b*TT + t;
        int id = g_argidx[r];
        if (eos) { g_mask[r] = 1; id = PAD_ID; }
        else       g_mask[r] = 0;
        if (ids_out) ids_out[r] = (float)id;
        if (id == EOS_ID) eos = 1;
    }
}

// ---------------- in-place softmax / one-hot masking ----------------
__global__ void k_softmax(float* __restrict__ probs) {
    __shared__ float ss[256];
    int r = blockIdx.x, tid = threadIdx.x;
    float* row = probs + (size_t)r*VV;
    if (g_mask[r]) {
        float4 z = make_float4(0.f,0.f,0.f,0.f);
        for (int j4 = tid; j4 < VV/4; j4 += 256) ((float4*)row)[j4] = z;
        if (tid == 0) row[PAD_ID] = 1.0f;
        return;
    }
    float m = g_rowmax[r];
    float s = 0.f;
    for (int j4 = tid; j4 < VV/4; j4 += 256) {
        float4 v = ((float4*)row)[j4];
        s += __expf(v.x-m) + __expf(v.y-m) + __expf(v.z-m) + __expf(v.w-m);
    }
    ss[tid] = s;
    __syncthreads();
    for (int st = 128; st > 0; st >>= 1) {
        if (tid < st) ss[tid] += ss[tid+st];
        __syncthreads();
    }
    float inv = 1.0f / ss[0];
    for (int j4 = tid; j4 < VV/4; j4 += 256) {
        float4 v = ((float4*)row)[j4];
        v.x = __expf(v.x-m)*inv; v.y = __expf(v.y-m)*inv;
        v.z = __expf(v.z-m)*inv; v.w = __expf(v.w-m)*inv;
        ((float4*)row)[j4] = v;
    }
}

extern "C" void kernel_launch(void* const* d_in, const int* in_sizes, int n_in,
                              void* d_out, int out_size) {
    const float* init_h  = (const float*)d_in[0];
    const float* init_c  = (const float*)d_in[1];
    const int*   init_in = (const int*)d_in[2];
    const int*   targets = (const int*)d_in[3];
    const float* emb     = (const float*)d_in[4];
    const float* embW    = (const float*)d_in[5];
    const float* W_ih    = (const float*)d_in[6];
    const float* W_hh    = (const float*)d_in[7];
    const float* b_ih    = (const float*)d_in[8];
    const float* b_hh    = (const float*)d_in[9];
    const float* W_out   = (const float*)d_in[10];
    const float* b_out   = (const float*)d_in[11];
    const float* aW1     = (const float*)d_in[12];
    const float* ab1     = (const float*)d_in[13];
    const float* aW2     = (const float*)d_in[14];
    const float* ab2     = (const float*)d_in[15];
    float* out = (float*)d_out;
    float* ids_out = ((size_t)out_size >= BTV + (size_t)NROW) ? out + BTV : nullptr;

    static bool attr_done = false;
    if (!attr_done) {
        cudaFuncSetAttribute(k_bf16_gemm, cudaFuncAttributeMaxDynamicSharedMemorySize,
                             GEMM_SMEM);
        attr_done = true;
    }
    float *Xep = nullptr, *gx0p = nullptr, *Xp = nullptr;
    __nv_bfloat16 *Whi_p = nullptr, *Wlo_p = nullptr, *Ahi_p = nullptr, *Alo_p = nullptr;
    cudaGetSymbolAddress((void**)&Xep,  g_Xe);
    cudaGetSymbolAddress((void**)&gx0p, g_gx0);
    cudaGetSymbolAddress((void**)&Xp,   g_X);
    cudaGetSymbolAddress((void**)&Whi_p, g_Whi);
    cudaGetSymbolAddress((void**)&Wlo_p, g_Wlo);
    cudaGetSymbolAddress((void**)&Ahi_p, g_Ahi);
    cudaGetSymbolAddress((void**)&Alo_p, g_Alo);

    k_attn_scores<<<BB*DD*LL, AH>>>(emb, aW1, ab1, aW2, ab2);
    k_attn_ctx<<<BB*LL, 256>>>(emb);
    k_ctx_gates<<<(LL*BB*G4)/8, 256>>>(W_hh, b_ih, b_hh);
    k_embed<<<(BB*TT*HH/4 + 255)/256, 256>>>(init_in, targets, embW);

    // gx0 = Xe @ W_ih[0]^T  (bf16x3 split)
    k_split<<<(NROW*HH/4 + 255)/256, 256>>>(Xep,  Ahi_p, Alo_p, NROW*HH/4);
    k_split<<<(G4*HH/4 + 255)/256, 256>>>(W_ih, Whi_p, Wlo_p, G4*HH/4);
    k_bf16_gemm<<<dim3(G4/256, NROW/128), 256, GEMM_SMEM>>>(
        Ahi_p, Alo_p, Whi_p, Wlo_p, nullptr, gx0p, G4);

    k_lstm<<<128, 256>>>(init_h, init_c, W_ih, W_hh);

    // logits = X @ W_out^T + b_out  (bf16x3 split)
    k_split<<<(NROW*HH/4 + 255)/256, 256>>>(Xp,    Ahi_p, Alo_p, NROW*HH/4);
    k_split<<<(VV*HH/4 + 255)/256, 256>>>(W_out, Whi_p, Wlo_p, VV*HH/4);
    k_bf16_gemm<<<dim3(VV/256, NROW/128), 256, GEMM_SMEM>>>(
        Ahi_p, Alo_p, Whi_p, Wlo_p, b_out, out, VV);

    k_argmax<<<NROW, 256>>>(out);
    k_eos<<<1, 32>>>(ids_out);
    k_softmax<<<NROW, 256>>>(out);
}

// round 9
// speedup vs baseline: 1.4746x; 1.2881x over previous
#include <cuda_runtime.h>
#include <cuda_bf16.h>
#include <cstdint>

#define BB   16
#define TT   128
#define VV   32000
#define HH   512
#define LL   2
#define DD   8
#define AH   256
#define G4   2048
#define PAD_ID 0
#define EOS_ID 3
#define NROW (BB*TT)            // 2048
#define BTV  ((size_t)NROW*VV)

// ---------------- device scratch ----------------
__device__ float g_scores[BB*DD*LL];
__device__ float g_ctx[BB*LL*HH];
__device__ float g_K[LL*BB*G4];
__device__ float g_Xe[NROW*HH];
__device__ float g_gx0[(size_t)NROW*G4];
__device__ float g_X[NROW*HH];
__device__ float g_h0[2][BB*HH];
__device__ float g_h1[2][BB*HH];
__device__ float g_c0[BB*HH];
__device__ float g_c1[BB*HH];
__device__ float g_rowmax[NROW];
__device__ int   g_argidx[NROW];
__device__ int   g_mask[NROW];
__device__ unsigned g_bcnt = 0;
__device__ unsigned g_bgen = 0;
// bf16 split scratch (weights + activations)
__device__ __nv_bfloat16 g_Whi[(size_t)VV*HH];
__device__ __nv_bfloat16 g_Wlo[(size_t)VV*HH];
__device__ __nv_bfloat16 g_Ahi[NROW*HH];
__device__ __nv_bfloat16 g_Alo[NROW*HH];

__device__ __forceinline__ float sigf(float x){ return 1.0f/(1.0f+__expf(-x)); }

// grid barrier (all CTAs resident)
__device__ __forceinline__ void gbar() {
    __threadfence();
    __syncthreads();
    if (threadIdx.x == 0) {
        volatile unsigned* vg = &g_bgen;
        unsigned g = *vg;
        unsigned a = atomicAdd(&g_bcnt, 1u);
        if (a == gridDim.x - 1u) {
            g_bcnt = 0;
            __threadfence();
            atomicAdd(&g_bgen, 1u);
        } else {
            while (*vg == g) { __nanosleep(64); }
        }
        __threadfence();
    }
    __syncthreads();
}

__device__ __forceinline__ float2 ldcg2(const float* p) {
    float2 v;
    asm volatile("ld.global.cg.v2.f32 {%0,%1}, [%2];" : "=f"(v.x), "=f"(v.y) : "l"(p));
    return v;
}

// ---------------- K1: attention scores  blk=(b*D+d)*L+l ----------------
__global__ void k_attn_scores(const float* __restrict__ emb, const float* __restrict__ W1,
                              const float* __restrict__ b1, const float* __restrict__ W2,
                              const float* __restrict__ b2) {
    __shared__ float se[HH];
    __shared__ float red[AH];
    int blk = blockIdx.x;
    const float* ep = emb + (size_t)blk * HH;
    for (int i = threadIdx.x; i < HH; i += AH) se[i] = ep[i];
    __syncthreads();
    int a = threadIdx.x;
    const float* w1 = W1 + (size_t)a * HH;
    float dot = 0.f;
    #pragma unroll 8
    for (int k = 0; k < HH; k++) dot += se[k] * w1[k];
    red[a] = tanhf(dot + b1[a]) * W2[a];
    __syncthreads();
    for (int s = AH/2; s > 0; s >>= 1) {
        if (a < s) red[a] += red[a + s];
        __syncthreads();
    }
    if (a == 0) g_scores[blk] = red[0] + b2[0];
}

// ---------------- K2: softmax over docs + context ----------------
__global__ void k_attn_ctx(const float* __restrict__ emb) {
    int b = blockIdx.x >> 1, l = blockIdx.x & 1;
    __shared__ float s[DD];
    if (threadIdx.x < DD) s[threadIdx.x] = g_scores[(b*DD + threadIdx.x)*LL + l];
    __syncthreads();
    float mx = -1e30f;
    #pragma unroll
    for (int d = 0; d < DD; d++) mx = fmaxf(mx, s[d]);
    float w[DD]; float sum = 0.f;
    #pragma unroll
    for (int d = 0; d < DD; d++) { w[d] = __expf(s[d] - mx); sum += w[d]; }
    float inv = 1.0f / sum;
    for (int h = threadIdx.x; h < HH; h += 256) {
        float acc = 0.f;
        #pragma unroll
        for (int d = 0; d < DD; d++)
            acc += w[d] * inv * emb[((size_t)(b*DD + d)*LL + l)*HH + h];
        g_ctx[(b*LL + l)*HH + h] = acc;
    }
}

// ---------------- K3: K[l][b][g] = 0.5*ctx@Whh^T + b_ih + b_hh ----------------
__global__ void k_ctx_gates(const float* __restrict__ Whh, const float* __restrict__ bih,
                            const float* __restrict__ bhh) {
    int out  = blockIdx.x * 8 + (threadIdx.x >> 5);
    int lane = threadIdx.x & 31;
    int l = out >> 15;
    int b = (out >> 11) & 15;
    int g = out & 2047;
    const float* wr = Whh + (size_t)l*G4*HH + (size_t)g*HH;
    const float* cx = g_ctx + (b*LL + l)*HH;
    float acc = 0.f;
    for (int k = lane; k < HH; k += 32) acc += wr[k]*cx[k];
    #pragma unroll
    for (int o = 16; o > 0; o >>= 1) acc += __shfl_xor_sync(0xffffffffu, acc, o);
    if (lane == 0) g_K[out] = 0.5f*acc + bih[l*G4 + g] + bhh[l*G4 + g];
}

// ---------------- K4: embedding gather ----------------
__global__ void k_embed(const int* __restrict__ init_input, const int* __restrict__ targets,
                        const float* __restrict__ embW) {
    int i4 = blockIdx.x * 256 + threadIdx.x;       // over B*T*H/4
    if (i4 >= BB*TT*HH/4) return;
    int r  = i4 >> 7;
    int h4 = i4 & 127;
    int b = r >> 7, t = r & 127;
    int tok = (t == 0) ? init_input[b] : targets[b*TT + t - 1];
    ((float4*)g_Xe)[i4] = ((const float4*)(embW + (size_t)tok*HH))[h4];
}

// ---------------- bf16 hi/lo split: hi=rn(v), lo=rn(v-hi) ----------------
__global__ void k_split(const float* __restrict__ src, __nv_bfloat16* __restrict__ hi,
                        __nv_bfloat16* __restrict__ lo, int n4) {
    int i = blockIdx.x*256 + threadIdx.x;
    if (i >= n4) return;
    float4 v = ((const float4*)src)[i];
    __nv_bfloat16 h0 = __float2bfloat16_rn(v.x);
    __nv_bfloat16 h1 = __float2bfloat16_rn(v.y);
    __nv_bfloat16 h2 = __float2bfloat16_rn(v.z);
    __nv_bfloat16 h3 = __float2bfloat16_rn(v.w);
    __nv_bfloat16 l0 = __float2bfloat16_rn(v.x - __bfloat162float(h0));
    __nv_bfloat16 l1 = __float2bfloat16_rn(v.y - __bfloat162float(h1));
    __nv_bfloat16 l2 = __float2bfloat16_rn(v.z - __bfloat162float(h2));
    __nv_bfloat16 l3 = __float2bfloat16_rn(v.w - __bfloat162float(h3));
    __nv_bfloat162* H = (__nv_bfloat162*)hi;
    __nv_bfloat162* L = (__nv_bfloat162*)lo;
    __nv_bfloat162 a; a.x = h0; a.y = h1;
    __nv_bfloat162 b; b.x = h2; b.y = h3;
    __nv_bfloat162 c; c.x = l0; c.y = l1;
    __nv_bfloat162 d; d.x = l2; d.y = l3;
    H[2*i] = a; H[2*i+1] = b;
    L[2*i] = c; L[2*i+1] = d;
}

// ================= bf16x3-split mma.sync GEMM (NT) =================
__device__ __forceinline__ void mma16(float* c, const uint32_t* a,
                                      uint32_t b0, uint32_t b1) {
    asm volatile("mma.sync.aligned.m16n8k16.row.col.f32.bf16.bf16.f32 "
        "{%0,%1,%2,%3}, {%4,%5,%6,%7}, {%8,%9}, {%0,%1,%2,%3};"
        : "+f"(c[0]), "+f"(c[1]), "+f"(c[2]), "+f"(c[3])
        : "r"(a[0]), "r"(a[1]), "r"(a[2]), "r"(a[3]), "r"(b0), "r"(b1));
}
__device__ __forceinline__ void cpasync16(uint32_t s, const void* g) {
    asm volatile("cp.async.ca.shared.global [%0], [%1], 16;" :: "r"(s), "l"(g));
}

#define SA    40
#define AHI_E 0
#define ALO_E (128*SA)
#define BHI_E (2*128*SA)
#define BLO_E (BHI_E + 256*SA)
#define STG_E (BLO_E + 256*SA)
#define GEMM_SMEM (2*STG_E*2)

__global__ __launch_bounds__(256) void k_bf16_gemm(
        const __nv_bfloat16* __restrict__ Ahi, const __nv_bfloat16* __restrict__ Alo,
        const __nv_bfloat16* __restrict__ Bhi, const __nv_bfloat16* __restrict__ Blo,
        const float* __restrict__ bias, float* __restrict__ C, int N) {
    extern __shared__ __nv_bfloat16 smb[];
    uint32_t sb = (uint32_t)__cvta_generic_to_shared(smb);
    int tid = threadIdx.x, lane = tid & 31, wid = tid >> 5;
    int wm = wid & 1, wn = wid >> 1;
    size_t bm = (size_t)blockIdx.y * 128;
    size_t bn = (size_t)blockIdx.x * 256;

    float acc[4][8][4];
    #pragma unroll
    for (int i = 0; i < 4; i++)
        #pragma unroll
        for (int j = 0; j < 8; j++)
            #pragma unroll
            for (int r = 0; r < 4; r++) acc[i][j][r] = 0.f;

    #define LOAD_STAGE(st) do { \
        uint32_t b_ = sb + (uint32_t)(((st) & 1) * (STG_E*2)); \
        int kc_ = (st) * 32; \
        _Pragma("unroll") \
        for (int j_ = 0; j_ < 2; j_++) { \
            int cid_ = tid + 256*j_; \
            int r_ = cid_ >> 2, ch_ = (cid_ & 3) * 8; \
            cpasync16(b_ + (uint32_t)(r_*SA + ch_)*2u, Ahi + (bm + r_)*512 + kc_ + ch_); \
            cpasync16(b_ + (uint32_t)(ALO_E + r_*SA + ch_)*2u, Alo + (bm + r_)*512 + kc_ + ch_); \
        } \
        _Pragma("unroll") \
        for (int j_ = 0; j_ < 4; j_++) { \
            int cid_ = tid + 256*j_; \
            int r_ = cid_ >> 2, ch_ = (cid_ & 3) * 8; \
            cpasync16(b_ + (uint32_t)(BHI_E + r_*SA + ch_)*2u, Bhi + (bn + r_)*512 + kc_ + ch_); \
            cpasync16(b_ + (uint32_t)(BLO_E + r_*SA + ch_)*2u, Blo + (bn + r_)*512 + kc_ + ch_); \
        } \
        asm volatile("cp.async.commit_group;"); \
    } while(0)

    LOAD_STAGE(0);

    for (int s = 0; s < 16; s++) {
        if (s + 1 < 16) {
            LOAD_STAGE(s + 1);
            asm volatile("cp.async.wait_group 1;");
        } else {
            asm volatile("cp.async.wait_group 0;");
        }
        __syncthreads();
        const __nv_bfloat16* Sb = smb + (s & 1) * STG_E;

        #pragma unroll
        for (int ks = 0; ks < 2; ks++) {
            int kc = ks*16 + (lane & 3)*2;
            uint32_t ah[4][4], al[4][4];
            #pragma unroll
            for (int mt = 0; mt < 4; mt++) {
                int r = wm*64 + mt*16 + (lane >> 2);
                const __nv_bfloat16* pa = Sb + AHI_E + r*SA + kc;
                const __nv_bfloat16* qa = Sb + ALO_E + r*SA + kc;
                ah[mt][0] = *(const uint32_t*)pa;
                ah[mt][1] = *(const uint32_t*)(pa + 8*SA);
                ah[mt][2] = *(const uint32_t*)(pa + 8);
                ah[mt][3] = *(const uint32_t*)(pa + 8*SA + 8);
                al[mt][0] = *(const uint32_t*)qa;
                al[mt][1] = *(const uint32_t*)(qa + 8*SA);
                al[mt][2] = *(const uint32_t*)(qa + 8);
                al[mt][3] = *(const uint32_t*)(qa + 8*SA + 8);
            }
            #pragma unroll
            for (int nt = 0; nt < 8; nt++) {
                int c = wn*64 + nt*8 + (lane >> 2);
                const __nv_bfloat16* pb = Sb + BHI_E + c*SA + kc;
                const __nv_bfloat16* qb = Sb + BLO_E + c*SA + kc;
                uint32_t bh0 = *(const uint32_t*)pb, bh1 = *(const uint32_t*)(pb + 8);
                uint32_t bl0 = *(const uint32_t*)qb, bl1 = *(const uint32_t*)(qb + 8);
                #pragma unroll
                for (int mt = 0; mt < 4; mt++) {
                    float* cc = acc[mt][nt];
                    mma16(cc, ah[mt], bh0, bh1);
                    mma16(cc, ah[mt], bl0, bl1);
                    mma16(cc, al[mt], bh0, bh1);
                }
            }
        }
        __syncthreads();
    }

    #pragma unroll
    for (int mt = 0; mt < 4; mt++) {
        size_t r0 = bm + wm*64 + mt*16 + (lane >> 2);
        #pragma unroll
        for (int nt = 0; nt < 8; nt++) {
            size_t c0 = bn + wn*64 + nt*8 + (lane & 3)*2;
            float b0 = bias ? bias[c0] : 0.f;
            float b1 = bias ? bias[c0 + 1] : 0.f;
            *(float2*)&C[r0*(size_t)N + c0] =
                make_float2(acc[mt][nt][0] + b0, acc[mt][nt][1] + b1);
            *(float2*)&C[(r0 + 8)*(size_t)N + c0] =
                make_float2(acc[mt][nt][2] + b0, acc[mt][nt][3] + b1);
        }
    }
    #undef LOAD_STAGE
}

// ---------------- fused persistent LSTM: smem weights + log-tree reduce ----------------
// 128 CTAs x 256 thr. Warp w: hout=blk*4+(w&3), khalf=w>>2.
// v[c*16+b]   : layer0 gates (t=s)     [uses matrix W0hh, pre-scaled 0.5]
// v[64+c*16+b]: layer1 gates (t=s-1)   [Wi1 (x=h0new) + 0.5*Wh1 (h1)]
#define LSMEM (48*512*4 + 8*128*4)      // 98304 + 4096 = 102400 bytes

__global__ __launch_bounds__(256,1) void k_lstm(const float* __restrict__ init_h,
                                                const float* __restrict__ init_c,
                                                const float* __restrict__ W_ih,
                                                const float* __restrict__ W_hh) {
    extern __shared__ float ws[];            // [48][512] weights, then sred[8][128]
    float* sred = ws + 48*512;
    int tid = threadIdx.x, lane = tid & 31, wid = tid >> 5;
    int hw = wid & 3, khalf = wid >> 2;

    // weights -> smem, pre-scaled (ALPHA fold). row r = m*16 + c*4 + hh
    for (int r = 0; r < 48; r++) {
        int m = r >> 4, c = (r >> 2) & 3, hh = r & 3;
        int row = blockIdx.x*4 + hh + c*512;
        const float* src; float sc;
        if (m == 0)      { src = W_hh + (size_t)row*HH;            sc = 0.5f; }
        else if (m == 1) { src = W_ih + 1048576 + (size_t)row*HH;  sc = 1.0f; }
        else             { src = W_hh + 1048576 + (size_t)row*HH;  sc = 0.5f; }
        for (int k = tid; k < HH; k += 256) ws[r*HH + k] = sc * src[k];
    }

    for (int i = blockIdx.x*256 + tid; i < BB*HH; i += gridDim.x*256) {
        int b = i >> 9, h = i & 511;
        g_h0[0][i] = init_h[b*1024 + h];
        g_h1[0][i] = init_h[b*1024 + 512 + h];
        g_c0[i]    = init_c[b*1024 + h];
        g_c1[i]    = init_c[b*1024 + 512 + h];
    }
    gbar();

    for (int s = 0; s <= TT; s++) {
        int p0 = s & 1;
        bool doL0 = (s < TT), doL1 = (s >= 1);
        const float* h0p = g_h0[p0];
        const float* h1p = g_h1[doL1 ? ((s - 1) & 1) : 0];

        float v[128];
        #pragma unroll
        for (int i = 0; i < 128; i++) v[i] = 0.f;

        // fused loop: matrices 0 (->accA) and 1 (->accB) share h0 loads
        #pragma unroll
        for (int kk = 0; kk < 4; kk++) {
            int kb = khalf*256 + kk*64 + lane*2;
            float2 hx[16];
            #pragma unroll
            for (int b = 0; b < 16; b++) hx[b] = ldcg2(h0p + b*HH + kb);
            #pragma unroll
            for (int c = 0; c < 4; c++) {
                float2 w0 = *(const float2*)&ws[(c*4 + hw)*HH + kb];
                float2 w1 = *(const float2*)&ws[((4 + c)*4 + hw)*HH + kb];
                #pragma unroll
                for (int b = 0; b < 16; b++) {
                    float a0 = v[c*16 + b], b0 = v[64 + c*16 + b];
                    a0 = fmaf(w0.x, hx[b].x, a0);
                    a0 = fmaf(w0.y, hx[b].y, a0);
                    b0 = fmaf(w1.x, hx[b].x, b0);
                    b0 = fmaf(w1.y, hx[b].y, b0);
                    v[c*16 + b] = a0; v[64 + c*16 + b] = b0;
                }
            }
        }
        // matrix 2 (h1 recurrent) -> accB
        #pragma unroll
        for (int kk = 0; kk < 4; kk++) {
            int kb = khalf*256 + kk*64 + lane*2;
            float2 hx[16];
            #pragma unroll
            for (int b = 0; b < 16; b++) hx[b] = ldcg2(h1p + b*HH + kb);
            #pragma unroll
            for (int c = 0; c < 4; c++) {
                float2 w2 = *(const float2*)&ws[((8 + c)*4 + hw)*HH + kb];
                #pragma unroll
                for (int b = 0; b < 16; b++) {
                    float b0 = v[64 + c*16 + b];
                    b0 = fmaf(w2.x, hx[b].x, b0);
                    b0 = fmaf(w2.y, hx[b].y, b0);
                    v[64 + c*16 + b] = b0;
                }
            }
        }

        // log-tree multi-value reduction: 128 values -> 4 per lane.
        // after all levels, lane l holds idx {4l..4l+3} at v[0..3].
        #pragma unroll
        for (int m = 16; m >= 1; m >>= 1) {
            int cnt = 4 * m;           // 64,32,16,8,4
            #pragma unroll
            for (int i = 0; i < 64; i++) {
                if (i < cnt) {
                    float send = (lane & m) ? v[i] : v[i + cnt];
                    float recv = __shfl_xor_sync(0xffffffffu, send, m);
                    v[i] = ((lane & m) ? v[i + cnt] : v[i]) + recv;
                }
            }
        }
        #pragma unroll
        for (int j = 0; j < 4; j++) sred[wid*128 + 4*lane + j] = v[j];
        __syncthreads();

        if (tid < 128) {
            int set = tid >> 6, b = (tid >> 2) & 15, hw2 = tid & 3;
            bool act = set ? doL1 : doL0;
            if (act) {
                int ho = blockIdx.x*4 + hw2;
                float g4[4];
                #pragma unroll
                for (int c = 0; c < 4; c++) {
                    int idx = set*64 + c*16 + b;
                    g4[c] = sred[hw2*128 + idx] + sred[(hw2 + 4)*128 + idx];
                }
                int si = b*HH + ho;
                if (set == 0) {
                    const float* Kp = g_K + b*G4;
                    const float* gx = g_gx0 + ((size_t)(b*TT + s))*G4;
                    float iv = g4[0] + Kp[ho]       + gx[ho];
                    float fv = g4[1] + Kp[ho+512]   + gx[ho+512];
                    float gv = g4[2] + Kp[ho+1024]  + gx[ho+1024];
                    float ov = g4[3] + Kp[ho+1536]  + gx[ho+1536];
                    float cn = sigf(fv)*g_c0[si] + sigf(iv)*tanhf(gv);
                    g_c0[si] = cn;
                    g_h0[p0^1][si] = sigf(ov)*tanhf(cn);
                } else {
                    const float* Kp = g_K + 32768 + b*G4;
                    float iv = g4[0] + Kp[ho];
                    float fv = g4[1] + Kp[ho+512];
                    float gv = g4[2] + Kp[ho+1024];
                    float ov = g4[3] + Kp[ho+1536];
                    float cn = sigf(fv)*g_c1[si] + sigf(iv)*tanhf(gv);
                    g_c1[si] = cn;
                    float hn = sigf(ov)*tanhf(cn);
                    g_h1[s & 1][si] = hn;
                    g_X[((size_t)(b*TT + (s-1)))*HH + ho] = hn;
                }
            }
        }
        gbar();
    }
}

// ---------------- per-row max + argmax over V ----------------
__global__ void k_argmax(const float* __restrict__ logits) {
    __shared__ float sm[256];
    __shared__ int   si[256];
    int r = blockIdx.x, tid = threadIdx.x;
    const float* row = logits + (size_t)r*VV;
    float bm = -1e30f; int bi = 0;
    for (int j = tid; j < VV; j += 256) {
        float v = row[j];
        if (v > bm || (v == bm && j < bi)) { bm = v; bi = j; }
    }
    sm[tid] = bm; si[tid] = bi;
    __syncthreads();
    for (int s = 128; s > 0; s >>= 1) {
        if (tid < s) {
            float v = sm[tid+s]; int i2 = si[tid+s];
            if (v > sm[tid] || (v == sm[tid] && i2 < si[tid])) { sm[tid] = v; si[tid] = i2; }
        }
        __syncthreads();
    }
    if (tid == 0) { g_rowmax[r] = sm[0]; g_argidx[r] = si[0]; }
}

// ---------------- sequential EOS scan + ids output ----------------
__global__ void k_eos(float* __restrict__ ids_out) {
    int b = threadIdx.x;
    if (b >= BB) return;
    int eos = 0;
    for (int t = 0; t < TT; t++) {
        int r = b*TT + t;
        int id = g_argidx[r];
        if (eos) { g_mask[r] = 1; id = PAD_ID; }
        else       g_mask[r] = 0;
        if (ids_out) ids_out[r] = (float)id;
        if (id == EOS_ID) eos = 1;
    }
}

// ---------------- in-place softmax / one-hot masking ----------------
__global__ void k_softmax(float* __restrict__ probs) {
    __shared__ float ss[256];
    int r = blockIdx.x, tid = threadIdx.x;
    float* row = probs + (size_t)r*VV;
    if (g_mask[r]) {
        float4 z = make_float4(0.f,0.f,0.f,0.f);
        for (int j4 = tid; j4 < VV/4; j4 += 256) ((float4*)row)[j4] = z;
        if (tid == 0) row[PAD_ID] = 1.0f;
        return;
    }
    float m = g_rowmax[r];
    float s = 0.f;
    for (int j4 = tid; j4 < VV/4; j4 += 256) {
        float4 v = ((float4*)row)[j4];
        s += __expf(v.x-m) + __expf(v.y-m) + __expf(v.z-m) + __expf(v.w-m);
    }
    ss[tid] = s;
    __syncthreads();
    for (int st = 128; st > 0; st >>= 1) {
        if (tid < st) ss[tid] += ss[tid+st];
        __syncthreads();
    }
    float inv = 1.0f / ss[0];
    for (int j4 = tid; j4 < VV/4; j4 += 256) {
        float4 v = ((float4*)row)[j4];
        v.x = __expf(v.x-m)*inv; v.y = __expf(v.y-m)*inv;
        v.z = __expf(v.z-m)*inv; v.w = __expf(v.w-m)*inv;
        ((float4*)row)[j4] = v;
    }
}

extern "C" void kernel_launch(void* const* d_in, const int* in_sizes, int n_in,
                              void* d_out, int out_size) {
    const float* init_h  = (const float*)d_in[0];
    const float* init_c  = (const float*)d_in[1];
    const int*   init_in = (const int*)d_in[2];
    const int*   targets = (const int*)d_in[3];
    const float* emb     = (const float*)d_in[4];
    const float* embW    = (const float*)d_in[5];
    const float* W_ih    = (const float*)d_in[6];
    const float* W_hh    = (const float*)d_in[7];
    const float* b_ih    = (const float*)d_in[8];
    const float* b_hh    = (const float*)d_in[9];
    const float* W_out   = (const float*)d_in[10];
    const float* b_out   = (const float*)d_in[11];
    const float* aW1     = (const float*)d_in[12];
    const float* ab1     = (const float*)d_in[13];
    const float* aW2     = (const float*)d_in[14];
    const float* ab2     = (const float*)d_in[15];
    float* out = (float*)d_out;
    float* ids_out = ((size_t)out_size >= BTV + (size_t)NROW) ? out + BTV : nullptr;

    static bool attr_done = false;
    if (!attr_done) {
        cudaFuncSetAttribute(k_bf16_gemm, cudaFuncAttributeMaxDynamicSharedMemorySize,
                             GEMM_SMEM);
        cudaFuncSetAttribute(k_lstm, cudaFuncAttributeMaxDynamicSharedMemorySize,
                             LSMEM);
        attr_done = true;
    }
    float *Xep = nullptr, *gx0p = nullptr, *Xp = nullptr;
    __nv_bfloat16 *Whi_p = nullptr, *Wlo_p = nullptr, *Ahi_p = nullptr, *Alo_p = nullptr;
    cudaGetSymbolAddress((void**)&Xep,  g_Xe);
    cudaGetSymbolAddress((void**)&gx0p, g_gx0);
    cudaGetSymbolAddress((void**)&Xp,   g_X);
    cudaGetSymbolAddress((void**)&Whi_p, g_Whi);
    cudaGetSymbolAddress((void**)&Wlo_p, g_Wlo);
    cudaGetSymbolAddress((void**)&Ahi_p, g_Ahi);
    cudaGetSymbolAddress((void**)&Alo_p, g_Alo);

    k_attn_scores<<<BB*DD*LL, AH>>>(emb, aW1, ab1, aW2, ab2);
    k_attn_ctx<<<BB*LL, 256>>>(emb);
    k_ctx_gates<<<(LL*BB*G4)/8, 256>>>(W_hh, b_ih, b_hh);
    k_embed<<<(BB*TT*HH/4 + 255)/256, 256>>>(init_in, targets, embW);

    // gx0 = Xe @ W_ih[0]^T  (bf16x3 split)
    k_split<<<(NROW*HH/4 + 255)/256, 256>>>(Xep,  Ahi_p, Alo_p, NROW*HH/4);
    k_split<<<(G4*HH/4 + 255)/256, 256>>>(W_ih, Whi_p, Wlo_p, G4*HH/4);
    k_bf16_gemm<<<dim3(G4/256, NROW/128), 256, GEMM_SMEM>>>(
        Ahi_p, Alo_p, Whi_p, Wlo_p, nullptr, gx0p, G4);

    k_lstm<<<128, 256, LSMEM>>>(init_h, init_c, W_ih, W_hh);

    // logits = X @ W_out^T + b_out  (bf16x3 split)
    k_split<<<(NROW*HH/4 + 255)/256, 256>>>(Xp,    Ahi_p, Alo_p, NROW*HH/4);
    k_split<<<(VV*HH/4 + 255)/256, 256>>>(W_out, Whi_p, Wlo_p, VV*HH/4);
    k_bf16_gemm<<<dim3(VV/256, NROW/128), 256, GEMM_SMEM>>>(
        Ahi_p, Alo_p, Whi_p, Wlo_p, b_out, out, VV);

    k_argmax<<<NROW, 256>>>(out);
    k_eos<<<1, 32>>>(ids_out);
    k_softmax<<<NROW, 256>>>(out);
}

// round 11
// speedup vs baseline: 1.6055x; 1.0888x over previous
#include <cuda_runtime.h>
#include <cuda_bf16.h>
#include <cstdint>

#define BB   16
#define TT   128
#define VV   32000
#define HH   512
#define LL   2
#define DD   8
#define AH   256
#define G4   2048
#define PAD_ID 0
#define EOS_ID 3
#define NROW (BB*TT)            // 2048
#define BTV  ((size_t)NROW*VV)

typedef unsigned long long u64;

// ---------------- device scratch ----------------
__device__ float g_scores[BB*DD*LL];
__device__ float g_ctx[BB*LL*HH];
__device__ float g_K[LL*BB*G4];
__device__ float g_Xe[NROW*HH];
__device__ float g_gx0[(size_t)NROW*G4];
__device__ float g_X[NROW*HH];
__device__ float g_h0[2][BB*HH];
__device__ float g_h1[2][BB*HH];
__device__ float g_c0[BB*HH];
__device__ float g_c1[BB*HH];
__device__ float g_rowmax[NROW];
__device__ float g_rowsum[NROW];
__device__ int   g_argidx[NROW];
__device__ int   g_mask[NROW];
__device__ unsigned g_bcnt = 0;
__device__ unsigned g_bgen = 0;
// bf16 split scratch (weights + activations)
__device__ __nv_bfloat16 g_Whi[(size_t)VV*HH];
__device__ __nv_bfloat16 g_Wlo[(size_t)VV*HH];
__device__ __nv_bfloat16 g_Ahi[NROW*HH];
__device__ __nv_bfloat16 g_Alo[NROW*HH];

__device__ __forceinline__ float sigf(float x){ return 1.0f/(1.0f+__expf(-x)); }

// grid barrier (all CTAs resident) — acquire-load hot spin
__device__ __forceinline__ void gbar() {
    __threadfence();
    __syncthreads();
    if (threadIdx.x == 0) {
        unsigned g;
        asm volatile("ld.acquire.gpu.b32 %0, [%1];" : "=r"(g) : "l"(&g_bgen));
        unsigned a = atomicAdd(&g_bcnt, 1u);
        if (a == gridDim.x - 1u) {
            g_bcnt = 0;
            __threadfence();
            atomicAdd(&g_bgen, 1u);
        } else {
            unsigned cur;
            do {
                asm volatile("ld.acquire.gpu.b32 %0, [%1];" : "=r"(cur) : "l"(&g_bgen));
            } while (cur == g);
        }
    }
    __syncthreads();
}

__device__ __forceinline__ u64 ldcg64(const float* p) {
    u64 v;
    asm volatile("ld.global.cg.b64 %0, [%1];" : "=l"(v) : "l"(p));
    return v;
}
__device__ __forceinline__ u64 fma2(u64 a, u64 b, u64 c) {
    u64 d;
    asm("fma.rn.f32x2 %0, %1, %2, %3;" : "=l"(d) : "l"(a), "l"(b), "l"(c));
    return d;
}
__device__ __forceinline__ void upk2(float& lo, float& hi, u64 v) {
    asm("mov.b64 {%0,%1}, %2;" : "=f"(lo), "=f"(hi) : "l"(v));
}

// ---------------- K1: attention scores  blk=(b*D+d)*L+l ----------------
__global__ void k_attn_scores(const float* __restrict__ emb, const float* __restrict__ W1,
                              const float* __restrict__ b1, const float* __restrict__ W2,
                              const float* __restrict__ b2) {
    __shared__ float se[HH];
    __shared__ float red[AH];
    int blk = blockIdx.x;
    const float* ep = emb + (size_t)blk * HH;
    for (int i = threadIdx.x; i < HH; i += AH) se[i] = ep[i];
    __syncthreads();
    int a = threadIdx.x;
    const float* w1 = W1 + (size_t)a * HH;
    float dot = 0.f;
    #pragma unroll 8
    for (int k = 0; k < HH; k++) dot += se[k] * w1[k];
    red[a] = tanhf(dot + b1[a]) * W2[a];
    __syncthreads();
    for (int s = AH/2; s > 0; s >>= 1) {
        if (a < s) red[a] += red[a + s];
        __syncthreads();
    }
    if (a == 0) g_scores[blk] = red[0] + b2[0];
}

// ---------------- K2: softmax over docs + context ----------------
__global__ void k_attn_ctx(const float* __restrict__ emb) {
    int b = blockIdx.x >> 1, l = blockIdx.x & 1;
    __shared__ float s[DD];
    if (threadIdx.x < DD) s[threadIdx.x] = g_scores[(b*DD + threadIdx.x)*LL + l];
    __syncthreads();
    float mx = -1e30f;
    #pragma unroll
    for (int d = 0; d < DD; d++) mx = fmaxf(mx, s[d]);
    float w[DD]; float sum = 0.f;
    #pragma unroll
    for (int d = 0; d < DD; d++) { w[d] = __expf(s[d] - mx); sum += w[d]; }
    float inv = 1.0f / sum;
    for (int h = threadIdx.x; h < HH; h += 256) {
        float acc = 0.f;
        #pragma unroll
        for (int d = 0; d < DD; d++)
            acc += w[d] * inv * emb[((size_t)(b*DD + d)*LL + l)*HH + h];
        g_ctx[(b*LL + l)*HH + h] = acc;
    }
}

// ---------------- K3: K[l][b][g] = 0.5*ctx@Whh^T + b_ih + b_hh ----------------
__global__ void k_ctx_gates(const float* __restrict__ Whh, const float* __restrict__ bih,
                            const float* __restrict__ bhh) {
    int out  = blockIdx.x * 8 + (threadIdx.x >> 5);
    int lane = threadIdx.x & 31;
    int l = out >> 15;
    int b = (out >> 11) & 15;
    int g = out & 2047;
    const float* wr = Whh + (size_t)l*G4*HH + (size_t)g*HH;
    const float* cx = g_ctx + (b*LL + l)*HH;
    float acc = 0.f;
    for (int k = lane; k < HH; k += 32) acc += wr[k]*cx[k];
    #pragma unroll
    for (int o = 16; o > 0; o >>= 1) acc += __shfl_xor_sync(0xffffffffu, acc, o);
    if (lane == 0) g_K[out] = 0.5f*acc + bih[l*G4 + g] + bhh[l*G4 + g];
}

// ---------------- K4: embedding gather ----------------
__global__ void k_embed(const int* __restrict__ init_input, const int* __restrict__ targets,
                        const float* __restrict__ embW) {
    int i4 = blockIdx.x * 256 + threadIdx.x;       // over B*T*H/4
    if (i4 >= BB*TT*HH/4) return;
    int r  = i4 >> 7;
    int h4 = i4 & 127;
    int b = r >> 7, t = r & 127;
    int tok = (t == 0) ? init_input[b] : targets[b*TT + t - 1];
    ((float4*)g_Xe)[i4] = ((const float4*)(embW + (size_t)tok*HH))[h4];
}

// ---------------- bf16 hi/lo split: hi=rn(v), lo=rn(v-hi) ----------------
__global__ void k_split(const float* __restrict__ src, __nv_bfloat16* __restrict__ hi,
                        __nv_bfloat16* __restrict__ lo, int n4) {
    int i = blockIdx.x*256 + threadIdx.x;
    if (i >= n4) return;
    float4 v = ((const float4*)src)[i];
    __nv_bfloat16 h0 = __float2bfloat16_rn(v.x);
    __nv_bfloat16 h1 = __float2bfloat16_rn(v.y);
    __nv_bfloat16 h2 = __float2bfloat16_rn(v.z);
    __nv_bfloat16 h3 = __float2bfloat16_rn(v.w);
    __nv_bfloat16 l0 = __float2bfloat16_rn(v.x - __bfloat162float(h0));
    __nv_bfloat16 l1 = __float2bfloat16_rn(v.y - __bfloat162float(h1));
    __nv_bfloat16 l2 = __float2bfloat16_rn(v.z - __bfloat162float(h2));
    __nv_bfloat16 l3 = __float2bfloat16_rn(v.w - __bfloat162float(h3));
    __nv_bfloat162* H = (__nv_bfloat162*)hi;
    __nv_bfloat162* L = (__nv_bfloat162*)lo;
    __nv_bfloat162 a; a.x = h0; a.y = h1;
    __nv_bfloat162 b; b.x = h2; b.y = h3;
    __nv_bfloat162 c; c.x = l0; c.y = l1;
    __nv_bfloat162 d; d.x = l2; d.y = l3;
    H[2*i] = a; H[2*i+1] = b;
    L[2*i] = c; L[2*i+1] = d;
}

// ================= bf16x3-split mma.sync GEMM (NT) =================
__device__ __forceinline__ void mma16(float* c, const uint32_t* a,
                                      uint32_t b0, uint32_t b1) {
    asm volatile("mma.sync.aligned.m16n8k16.row.col.f32.bf16.bf16.f32 "
        "{%0,%1,%2,%3}, {%4,%5,%6,%7}, {%8,%9}, {%0,%1,%2,%3};"
        : "+f"(c[0]), "+f"(c[1]), "+f"(c[2]), "+f"(c[3])
        : "r"(a[0]), "r"(a[1]), "r"(a[2]), "r"(a[3]), "r"(b0), "r"(b1));
}
__device__ __forceinline__ void cpasync16(uint32_t s, const void* g) {
    asm volatile("cp.async.ca.shared.global [%0], [%1], 16;" :: "r"(s), "l"(g));
}

#define SA    40
#define AHI_E 0
#define ALO_E (128*SA)
#define BHI_E (2*128*SA)
#define BLO_E (BHI_E + 256*SA)
#define STG_E (BLO_E + 256*SA)
#define GEMM_SMEM (2*STG_E*2)

__global__ __launch_bounds__(256) void k_bf16_gemm(
        const __nv_bfloat16* __restrict__ Ahi, const __nv_bfloat16* __restrict__ Alo,
        const __nv_bfloat16* __restrict__ Bhi, const __nv_bfloat16* __restrict__ Blo,
        const float* __restrict__ bias, float* __restrict__ C, int N) {
    extern __shared__ __nv_bfloat16 smb[];
    uint32_t sb = (uint32_t)__cvta_generic_to_shared(smb);
    int tid = threadIdx.x, lane = tid & 31, wid = tid >> 5;
    int wm = wid & 1, wn = wid >> 1;
    size_t bm = (size_t)blockIdx.y * 128;
    size_t bn = (size_t)blockIdx.x * 256;

    float acc[4][8][4];
    #pragma unroll
    for (int i = 0; i < 4; i++)
        #pragma unroll
        for (int j = 0; j < 8; j++)
            #pragma unroll
            for (int r = 0; r < 4; r++) acc[i][j][r] = 0.f;

    #define LOAD_STAGE(st) do { \
        uint32_t b_ = sb + (uint32_t)(((st) & 1) * (STG_E*2)); \
        int kc_ = (st) * 32; \
        _Pragma("unroll") \
        for (int j_ = 0; j_ < 2; j_++) { \
            int cid_ = tid + 256*j_; \
            int r_ = cid_ >> 2, ch_ = (cid_ & 3) * 8; \
            cpasync16(b_ + (uint32_t)(r_*SA + ch_)*2u, Ahi + (bm + r_)*512 + kc_ + ch_); \
            cpasync16(b_ + (uint32_t)(ALO_E + r_*SA + ch_)*2u, Alo + (bm + r_)*512 + kc_ + ch_); \
        } \
        _Pragma("unroll") \
        for (int j_ = 0; j_ < 4; j_++) { \
            int cid_ = tid + 256*j_; \
            int r_ = cid_ >> 2, ch_ = (cid_ & 3) * 8; \
            cpasync16(b_ + (uint32_t)(BHI_E + r_*SA + ch_)*2u, Bhi + (bn + r_)*512 + kc_ + ch_); \
            cpasync16(b_ + (uint32_t)(BLO_E + r_*SA + ch_)*2u, Blo + (bn + r_)*512 + kc_ + ch_); \
        } \
        asm volatile("cp.async.commit_group;"); \
    } while(0)

    LOAD_STAGE(0);

    for (int s = 0; s < 16; s++) {
        if (s + 1 < 16) {
            LOAD_STAGE(s + 1);
            asm volatile("cp.async.wait_group 1;");
        } else {
            asm volatile("cp.async.wait_group 0;");
        }
        __syncthreads();
        const __nv_bfloat16* Sb = smb + (s & 1) * STG_E;

        #pragma unroll
        for (int ks = 0; ks < 2; ks++) {
            int kc = ks*16 + (lane & 3)*2;
            uint32_t ah[4][4], al[4][4];
            #pragma unroll
            for (int mt = 0; mt < 4; mt++) {
                int r = wm*64 + mt*16 + (lane >> 2);
                const __nv_bfloat16* pa = Sb + AHI_E + r*SA + kc;
                const __nv_bfloat16* qa = Sb + ALO_E + r*SA + kc;
                ah[mt][0] = *(const uint32_t*)pa;
                ah[mt][1] = *(const uint32_t*)(pa + 8*SA);
                ah[mt][2] = *(const uint32_t*)(pa + 8);
                ah[mt][3] = *(const uint32_t*)(pa + 8*SA + 8);
                al[mt][0] = *(const uint32_t*)qa;
                al[mt][1] = *(const uint32_t*)(qa + 8*SA);
                al[mt][2] = *(const uint32_t*)(qa + 8);
                al[mt][3] = *(const uint32_t*)(qa + 8*SA + 8);
            }
            #pragma unroll
            for (int nt = 0; nt < 8; nt++) {
                int c = wn*64 + nt*8 + (lane >> 2);
                const __nv_bfloat16* pb = Sb + BHI_E + c*SA + kc;
                const __nv_bfloat16* qb = Sb + BLO_E + c*SA + kc;
                uint32_t bh0 = *(const uint32_t*)pb, bh1 = *(const uint32_t*)(pb + 8);
                uint32_t bl0 = *(const uint32_t*)qb, bl1 = *(const uint32_t*)(qb + 8);
                #pragma unroll
                for (int mt = 0; mt < 4; mt++) {
                    float* cc = acc[mt][nt];
                    mma16(cc, ah[mt], bh0, bh1);
                    mma16(cc, ah[mt], bl0, bl1);
                    mma16(cc, al[mt], bh0, bh1);
                }
            }
        }
        __syncthreads();
    }

    #pragma unroll
    for (int mt = 0; mt < 4; mt++) {
        size_t r0 = bm + wm*64 + mt*16 + (lane >> 2);
        #pragma unroll
        for (int nt = 0; nt < 8; nt++) {
            size_t c0 = bn + wn*64 + nt*8 + (lane & 3)*2;
            float b0 = bias ? bias[c0] : 0.f;
            float b1 = bias ? bias[c0 + 1] : 0.f;
            *(float2*)&C[r0*(size_t)N + c0] =
                make_float2(acc[mt][nt][0] + b0, acc[mt][nt][1] + b1);
            *(float2*)&C[(r0 + 8)*(size_t)N + c0] =
                make_float2(acc[mt][nt][2] + b0, acc[mt][nt][3] + b1);
        }
    }
    #undef LOAD_STAGE
}

// ---------------- fused persistent LSTM: FFMA2 over K-pairs ----------------
// 128 CTAs x 256 thr (8 warps). Warp w: hw=w&3 (h-index in CTA), bh=w>>2 (batch half).
// Each warp covers full K=512 (16 k per lane, paired even/odd in f32x2), 8 batches.
// vA[c*8+bl]: layer0 gates (t=s); vB[c*8+bl]: layer1 gates (t=s-1).
#define LSMEM (48*512*4 + 8*64*4)       // 98304 + 2048 = 100352 bytes

__global__ __launch_bounds__(256,1) void k_lstm(const float* __restrict__ init_h,
                                                const float* __restrict__ init_c,
                                                const float* __restrict__ W_ih,
                                                const float* __restrict__ W_hh) {
    extern __shared__ float ws[];            // [48][512] weights, then sred[8][64]
    float* sred = ws + 48*512;
    int tid = threadIdx.x, lane = tid & 31, wid = tid >> 5;
    int hw = wid & 3, bh = wid >> 2;

    // weights -> smem, pre-scaled (ALPHA fold). row r = m*16 + c*4 + hh
    for (int r = 0; r < 48; r++) {
        int m = r >> 4, c = (r >> 2) & 3, hh = r & 3;
        int row = blockIdx.x*4 + hh + c*512;
        const float* src; float sc;
        if (m == 0)      { src = W_hh + (size_t)row*HH;            sc = 0.5f; }
        else if (m == 1) { src = W_ih + 1048576 + (size_t)row*HH;  sc = 1.0f; }
        else             { src = W_hh + 1048576 + (size_t)row*HH;  sc = 0.5f; }
        for (int k = tid; k < HH; k += 256) ws[r*HH + k] = sc * src[k];
    }

    for (int i = blockIdx.x*256 + tid; i < BB*HH; i += gridDim.x*256) {
        int b = i >> 9, h = i & 511;
        g_h0[0][i] = init_h[b*1024 + h];
        g_h1[0][i] = init_h[b*1024 + 512 + h];
        g_c0[i]    = init_c[b*1024 + h];
        g_c1[i]    = init_c[b*1024 + 512 + h];
    }
    gbar();

    for (int s = 0; s <= TT; s++) {
        int p0 = s & 1;
        bool doL0 = (s < TT), doL1 = (s >= 1);
        const float* h0p = g_h0[p0];
        const float* h1p = g_h1[doL1 ? ((s - 1) & 1) : 0];

        u64 vA[32], vB[32];
        #pragma unroll
        for (int i = 0; i < 32; i++) { vA[i] = 0ull; vB[i] = 0ull; }

        // section h0: matrices 0 (->vA) and 1 (->vB) share h0 loads
        #pragma unroll
        for (int j = 0; j < 8; j++) {
            int k = lane*2 + j*64;
            u64 hp[8];
            #pragma unroll
            for (int b = 0; b < 8; b++) hp[b] = ldcg64(h0p + (bh*8 + b)*HH + k);
            #pragma unroll
            for (int c = 0; c < 4; c++) {
                u64 w0 = *(const u64*)&ws[(c*4 + hw)*HH + k];
                u64 w1 = *(const u64*)&ws[((4 + c)*4 + hw)*HH + k];
                #pragma unroll
                for (int b = 0; b < 8; b++) {
                    vA[c*8 + b] = fma2(w0, hp[b], vA[c*8 + b]);
                    vB[c*8 + b] = fma2(w1, hp[b], vB[c*8 + b]);
                }
            }
        }
        // section h1: matrix 2 (->vB)
        #pragma unroll
        for (int j = 0; j < 8; j++) {
            int k = lane*2 + j*64;
            u64 hp[8];
            #pragma unroll
            for (int b = 0; b < 8; b++) hp[b] = ldcg64(h1p + (bh*8 + b)*HH + k);
            #pragma unroll
            for (int c = 0; c < 4; c++) {
                u64 w2 = *(const u64*)&ws[((8 + c)*4 + hw)*HH + k];
                #pragma unroll
                for (int b = 0; b < 8; b++)
                    vB[c*8 + b] = fma2(w2, hp[b], vB[c*8 + b]);
            }
        }

        // unpack even/odd partials -> v[64]
        float v[64];
        #pragma unroll
        for (int i = 0; i < 32; i++) {
            float lo, hi;
            upk2(lo, hi, vA[i]); v[i] = lo + hi;
            upk2(lo, hi, vB[i]); v[32 + i] = lo + hi;
        }

        // log-tree reduction: 64 values -> 2 per lane; lane l holds idx {2l, 2l+1}
        #pragma unroll
        for (int m = 16; m >= 1; m >>= 1) {
            int cnt = 2 * m;           // 32,16,8,4,2
            #pragma unroll
            for (int i = 0; i < 32; i++) {
                if (i < cnt) {
                    float send = (lane & m) ? v[i] : v[i + cnt];
                    float recv = __shfl_xor_sync(0xffffffffu, send, m);
                    v[i] = ((lane & m) ? v[i + cnt] : v[i]) + recv;
                }
            }
        }
        sred[wid*64 + 2*lane]     = v[0];
        sred[wid*64 + 2*lane + 1] = v[1];
        __syncthreads();

        if (tid < 128) {
            int set = tid >> 6, b = (tid >> 2) & 15, hw2 = tid & 3;
            bool act = set ? doL1 : doL0;
            if (act) {
                int ho = blockIdx.x*4 + hw2;
                int w = (b >> 3)*4 + hw2;
                float g4[4];
                #pragma unroll
                for (int c = 0; c < 4; c++)
                    g4[c] = sred[w*64 + set*32 + c*8 + (b & 7)];
                int si = b*HH + ho;
                if (set == 0) {
                    const float* Kp = g_K + b*G4;
                    const float* gx = g_gx0 + ((size_t)(b*TT + s))*G4;
                    float iv = g4[0] + Kp[ho]       + gx[ho];
                    float fv = g4[1] + Kp[ho+512]   + gx[ho+512];
                    float gv = g4[2] + Kp[ho+1024]  + gx[ho+1024];
                    float ov = g4[3] + Kp[ho+1536]  + gx[ho+1536];
                    float cn = sigf(fv)*g_c0[si] + sigf(iv)*tanhf(gv);
                    g_c0[si] = cn;
                    g_h0[p0^1][si] = sigf(ov)*tanhf(cn);
                } else {
                    const float* Kp = g_K + 32768 + b*G4;
                    float iv = g4[0] + Kp[ho];
                    float fv = g4[1] + Kp[ho+512];
                    float gv = g4[2] + Kp[ho+1024];
                    float ov = g4[3] + Kp[ho+1536];
                    float cn = sigf(fv)*g_c1[si] + sigf(iv)*tanhf(gv);
                    g_c1[si] = cn;
                    float hn = sigf(ov)*tanhf(cn);
                    g_h1[s & 1][si] = hn;
                    g_X[((size_t)(b*TT + (s-1)))*HH + ho] = hn;
                }
            }
        }
        gbar();
    }
}

// ---------------- per-row max + argmax + exp-sum over V ----------------
__global__ void k_argmax(const float* __restrict__ logits) {
    __shared__ float sm[256];
    __shared__ int   si[256];
    int r = blockIdx.x, tid = threadIdx.x;
    const float* row = logits + (size_t)r*VV;
    float bm = -1e30f; int bi = 0;
    for (int j = tid; j < VV; j += 256) {
        float v = row[j];
        if (v > bm || (v == bm && j < bi)) { bm = v; bi = j; }
    }
    sm[tid] = bm; si[tid] = bi;
    __syncthreads();
    for (int s = 128; s > 0; s >>= 1) {
        if (tid < s) {
            float v = sm[tid+s]; int i2 = si[tid+s];
            if (v > sm[tid] || (v == sm[tid] && i2 < si[tid])) { sm[tid] = v; si[tid] = i2; }
        }
        __syncthreads();
    }
    float m = sm[0];
    if (tid == 0) { g_rowmax[r] = m; g_argidx[r] = si[0]; }
    __syncthreads();
    // exp-sum (row now L2-resident)
    float s = 0.f;
    for (int j4 = tid; j4 < VV/4; j4 += 256) {
        float4 v = ((const float4*)row)[j4];
        s += __expf(v.x-m) + __expf(v.y-m) + __expf(v.z-m) + __expf(v.w-m);
    }
    sm[tid] = s;
    __syncthreads();
    for (int st = 128; st > 0; st >>= 1) {
        if (tid < st) sm[tid] += sm[tid+st];
        __syncthreads();
    }
    if (tid == 0) g_rowsum[r] = sm[0];
}

// ---------------- sequential EOS scan + ids output ----------------
__global__ void k_eos(float* __restrict__ ids_out) {
    int b = threadIdx.x;
    if (b >= BB) return;
    int eos = 0;
    for (int t = 0; t < TT; t++) {
        int r = b*TT + t;
        int id = g_argidx[r];
        if (eos) { g_mask[r] = 1; id = PAD_ID; }
        else       g_mask[r] = 0;
        if (ids_out) ids_out[r] = (float)id;
        if (id == EOS_ID) eos = 1;
    }
}

// ---------------- in-place softmax / one-hot masking (single pass) ----------------
__global__ void k_softmax(float* __restrict__ probs) {
    int r = blockIdx.x, tid = threadIdx.x;
    float* row = probs + (size_t)r*VV;
    if (g_mask[r]) {
        float4 z = make_float4(0.f,0.f,0.f,0.f);
        for (int j4 = tid; j4 < VV/4; j4 += 256) ((float4*)row)[j4] = z;
        if (tid == 0) row[PAD_ID] = 1.0f;
        return;
    }
    float m = g_rowmax[r];
    float inv = 1.0f / g_rowsum[r];
    for (int j4 = tid; j4 < VV/4; j4 += 256) {
        float4 v = ((float4*)row)[j4];
        v.x = __expf(v.x-m)*inv; v.y = __expf(v.y-m)*inv;
        v.z = __expf(v.z-m)*inv; v.w = __expf(v.w-m)*inv;
        ((float4*)row)[j4] = v;
    }
}

extern "C" void kernel_launch(void* const* d_in, const int* in_sizes, int n_in,
                              void* d_out, int out_size) {
    const float* init_h  = (const float*)d_in[0];
    const float* init_c  = (const float*)d_in[1];
    const int*   init_in = (const int*)d_in[2];
    const int*   targets = (const int*)d_in[3];
    const float* emb     = (const float*)d_in[4];
    const float* embW    = (const float*)d_in[5];
    const float* W_ih    = (const float*)d_in[6];
    const float* W_hh    = (const float*)d_in[7];
    const float* b_ih    = (const float*)d_in[8];
    const float* b_hh    = (const float*)d_in[9];
    const float* W_out   = (const float*)d_in[10];
    const float* b_out   = (const float*)d_in[11];
    const float* aW1     = (const float*)d_in[12];
    const float* ab1     = (const float*)d_in[13];
    const float* aW2     = (const float*)d_in[14];
    const float* ab2     = (const float*)d_in[15];
    float* out = (float*)d_out;
    float* ids_out = ((size_t)out_size >= BTV + (size_t)NROW) ? out + BTV : nullptr;

    static bool attr_done = false;
    if (!attr_done) {
        cudaFuncSetAttribute(k_bf16_gemm, cudaFuncAttributeMaxDynamicSharedMemorySize,
                             GEMM_SMEM);
        cudaFuncSetAttribute(k_lstm, cudaFuncAttributeMaxDynamicSharedMemorySize,
                             LSMEM);
        attr_done = true;
    }
    float *Xep = nullptr, *gx0p = nullptr, *Xp = nullptr;
    __nv_bfloat16 *Whi_p = nullptr, *Wlo_p = nullptr, *Ahi_p = nullptr, *Alo_p = nullptr;
    cudaGetSymbolAddress((void**)&Xep,  g_Xe);
    cudaGetSymbolAddress((void**)&gx0p, g_gx0);
    cudaGetSymbolAddress((void**)&Xp,   g_X);
    cudaGetSymbolAddress((void**)&Whi_p, g_Whi);
    cudaGetSymbolAddress((void**)&Wlo_p, g_Wlo);
    cudaGetSymbolAddress((void**)&Ahi_p, g_Ahi);
    cudaGetSymbolAddress((void**)&Alo_p, g_Alo);

    k_attn_scores<<<BB*DD*LL, AH>>>(emb, aW1, ab1, aW2, ab2);
    k_attn_ctx<<<BB*LL, 256>>>(emb);
    k_ctx_gates<<<(LL*BB*G4)/8, 256>>>(W_hh, b_ih, b_hh);
    k_embed<<<(BB*TT*HH/4 + 255)/256, 256>>>(init_in, targets, embW);

    // gx0 = Xe @ W_ih[0]^T  (bf16x3 split)
    k_split<<<(NROW*HH/4 + 255)/256, 256>>>(Xep,  Ahi_p, Alo_p, NROW*HH/4);
    k_split<<<(G4*HH/4 + 255)/256, 256>>>(W_ih, Whi_p, Wlo_p, G4*HH/4);
    k_bf16_gemm<<<dim3(G4/256, NROW/128), 256, GEMM_SMEM>>>(
        Ahi_p, Alo_p, Whi_p, Wlo_p, nullptr, gx0p, G4);

    k_lstm<<<128, 256, LSMEM>>>(init_h, init_c, W_ih, W_hh);

    // logits = X @ W_out^T + b_out  (bf16x3 split)
    k_split<<<(NROW*HH/4 + 255)/256, 256>>>(Xp,    Ahi_p, Alo_p, NROW*HH/4);
    k_split<<<(VV*HH/4 + 255)/256, 256>>>(W_out, Whi_p, Wlo_p, VV*HH/4);
    k_bf16_gemm<<<dim3(VV/256, NROW/128), 256, GEMM_SMEM>>>(
        Ahi_p, Alo_p, Whi_p, Wlo_p, b_out, out, VV);

    k_argmax<<<NROW, 256>>>(out);
    k_eos<<<1, 32>>>(ids_out);
    k_softmax<<<NROW, 256>>>(out);
}